// round 5
// baseline (speedup 1.0000x reference)
#include <cuda_runtime.h>
#include <cuda_bf16.h>
#include <cstdint>

// Problem constants
#define HB   4
#define HS   1024
#define HD   1024
#define HH   16
#define HDK  64
#define MTOT (HB*HS)          // 4096
#define NBH  (HB*HH)          // 64
#define OUT_ELEMS (MTOT*HD)   // 4194304

// Scratch (allocation-free device globals)
__device__ __nv_bfloat16 g_Xhi[3*MTOT*HD];   // split inputs q,k,v; slot0 reused for ctx
__device__ __nv_bfloat16 g_Xlo[3*MTOT*HD];
__device__ __nv_bfloat16 g_Whi[4*HD*HD];     // W^T [n][k] for Wq,Wk,Wv,Wo
__device__ __nv_bfloat16 g_Wlo[4*HD*HD];
__device__ __nv_bfloat16 g_Qhi[NBH*HS*HDK];  // [bh][s][d] pre-scaled
__device__ __nv_bfloat16 g_Qlo[NBH*HS*HDK];
__device__ __nv_bfloat16 g_Khi[NBH*HS*HDK];
__device__ __nv_bfloat16 g_Klo[NBH*HS*HDK];
__device__ float         g_Vf [NBH*HS*HDK];  // [bh][s][d] fp32
__device__ __nv_bfloat16 g_VThi[NBH*HDK*HS]; // [bh][d][s]
__device__ __nv_bfloat16 g_VTlo[NBH*HDK*HS];

// ---------------------------------------------------------------------------
// helpers
// ---------------------------------------------------------------------------
__device__ __forceinline__ uint32_t smem_u32(const void* p) {
    uint32_t a;
    asm("{ .reg .u64 t; cvta.to.shared.u64 t, %1; cvt.u32.u64 %0, t; }"
        : "=r"(a) : "l"(p));
    return a;
}
__device__ __forceinline__ void ldmx4(uint32_t* r, uint32_t addr) {
    asm volatile("ldmatrix.sync.aligned.m8n8.x4.shared.b16 {%0,%1,%2,%3}, [%4];"
        : "=r"(r[0]), "=r"(r[1]), "=r"(r[2]), "=r"(r[3]) : "r"(addr));
}
__device__ __forceinline__ void mma_bf16(float* c, const uint32_t* a,
                                         uint32_t b0, uint32_t b1) {
    asm volatile(
        "mma.sync.aligned.m16n8k16.row.col.f32.bf16.bf16.f32 "
        "{%0,%1,%2,%3}, {%4,%5,%6,%7}, {%8,%9}, {%0,%1,%2,%3};"
        : "+f"(c[0]), "+f"(c[1]), "+f"(c[2]), "+f"(c[3])
        : "r"(a[0]), "r"(a[1]), "r"(a[2]), "r"(a[3]), "r"(b0), "r"(b1));
}
__device__ __forceinline__ void split2(float x, float y,
                                       uint32_t& hi, uint32_t& lo) {
    __nv_bfloat16 hx = __float2bfloat16(x), hy = __float2bfloat16(y);
    __nv_bfloat16 lx = __float2bfloat16(x - __bfloat162float(hx));
    __nv_bfloat16 ly = __float2bfloat16(y - __bfloat162float(hy));
    __nv_bfloat162 h2(hx, hy), l2(lx, ly);
    hi = *(uint32_t*)&h2;
    lo = *(uint32_t*)&l2;
}
#define CP16(dst, src) asm volatile("cp.async.cg.shared.global [%0], [%1], 16;" :: "r"(dst), "l"(src))
#define CP_COMMIT()    asm volatile("cp.async.commit_group;" ::: "memory")
#define CP_WAIT1()     asm volatile("cp.async.wait_group 1;" ::: "memory")
#define CP_WAIT0()     asm volatile("cp.async.wait_group 0;" ::: "memory")

// ---------------------------------------------------------------------------
// q,k,v fp32 -> (hi, lo) bf16 split, one launch
// ---------------------------------------------------------------------------
#define N4 (OUT_ELEMS/4)
__global__ __launch_bounds__(256)
void splitQKV_k(const float4* __restrict__ q, const float4* __restrict__ k,
                const float4* __restrict__ v)
{
    int i = blockIdx.x * 256 + threadIdx.x;          // 0 .. 3*N4
    int z = i / N4, j = i - z * N4;
    const float4* src = (z == 0) ? q : (z == 1) ? k : v;
    float4 val = src[j];
    uint32_t* hi = (uint32_t*)(g_Xhi + (size_t)z * OUT_ELEMS);
    uint32_t* lo = (uint32_t*)(g_Xlo + (size_t)z * OUT_ELEMS);
    uint32_t h0, l0, h1, l1;
    split2(val.x, val.y, h0, l0);
    split2(val.z, val.w, h1, l1);
    hi[2*j] = h0; hi[2*j+1] = h1;
    lo[2*j] = l0; lo[2*j+1] = l1;
}

// ---------------------------------------------------------------------------
// All 4 weights: W[k][n] fp32 -> W^T hi/lo [n][k] bf16, one launch
// ---------------------------------------------------------------------------
__global__ __launch_bounds__(256)
void wT4_k(const float* __restrict__ Wq, const float* __restrict__ Wk,
           const float* __restrict__ Wv, const float* __restrict__ Wo)
{
    __shared__ float t[32][33];
    const int z = blockIdx.z;
    const float* W = (z == 0) ? Wq : (z == 1) ? Wk : (z == 2) ? Wv : Wo;
    __nv_bfloat16* hiT = g_Whi + (size_t)z * HD * HD;
    __nv_bfloat16* loT = g_Wlo + (size_t)z * HD * HD;
    int k0 = blockIdx.y * 32, n0 = blockIdx.x * 32;
    int tx = threadIdx.x, ty = threadIdx.y;   // (32, 8)
#pragma unroll
    for (int j = 0; j < 32; j += 8)
        t[ty + j][tx] = W[(size_t)(k0 + ty + j) * HD + n0 + tx];
    __syncthreads();
#pragma unroll
    for (int j = 0; j < 32; j += 8) {
        float v = t[tx][ty + j];
        __nv_bfloat16 h = __float2bfloat16(v);
        __nv_bfloat16 l = __float2bfloat16(v - __bfloat162float(h));
        size_t o = (size_t)(n0 + ty + j) * HD + k0 + tx;
        hiT[o] = h;
        loT[o] = l;
    }
}

// ---------------------------------------------------------------------------
// g_Vf [bh][s][d] -> g_VThi/lo [bh][d][s]
// ---------------------------------------------------------------------------
__global__ __launch_bounds__(256)
void vT_split_k()
{
    __shared__ float t[32][33];
    int bh = blockIdx.y;
    int s0 = (blockIdx.x & 31) * 32;
    int d0 = (blockIdx.x >> 5) * 32;
    int tx = threadIdx.x, ty = threadIdx.y;   // (32, 8)
    const float* V = g_Vf + (size_t)bh * HS * HDK;
#pragma unroll
    for (int j = 0; j < 32; j += 8)
        t[ty + j][tx] = V[(size_t)(s0 + ty + j) * HDK + d0 + tx];
    __syncthreads();
    __nv_bfloat16* Hi = g_VThi + (size_t)bh * HDK * HS;
    __nv_bfloat16* Lo = g_VTlo + (size_t)bh * HDK * HS;
#pragma unroll
    for (int j = 0; j < 32; j += 8) {
        float v = t[tx][ty + j];
        __nv_bfloat16 h = __float2bfloat16(v);
        __nv_bfloat16 l = __float2bfloat16(v - __bfloat162float(h));
        size_t o = (size_t)(d0 + ty + j) * HS + s0 + tx;
        Hi[o] = h;
        Lo[o] = l;
    }
}

// ---------------------------------------------------------------------------
// Dense GEMM (BM=128,BN=128,BK=32), cp.async 3-stage, split-bf16 (3 MMAs).
// PROJ=true: blockIdx.z in {0,1,2} = Q/K/V with fused epilogues.
// PROJ=false: out = ctx @ Wo + bo, fp32 row-major.
// ---------------------------------------------------------------------------
#define GSTR 80                     // 64B data + 16 pad
#define GMAT (128*GSTR)             // 10240
#define GSTAGE (4*GMAT)             // 40960 (Ahi,Alo,Bhi,Blo)
#define GT_SMEM (3*GSTAGE)          // 122880

template<bool PROJ>
__global__ __launch_bounds__(256, 1)
void gemm5(const float* __restrict__ b0, const float* __restrict__ b1,
           const float* __restrict__ b2, float* __restrict__ outp)
{
    extern __shared__ char sm[];
    const uint32_t sb = smem_u32(sm);
    const int z = PROJ ? blockIdx.z : 3;
    const int tid = threadIdx.x;
    const int wid = tid >> 5, lane = tid & 31;
    const int wm = wid & 3, wn = wid >> 2;
    const int m0 = blockIdx.y * 128, n0 = blockIdx.x * 128;

    const __nv_bfloat16* Xhi = g_Xhi + (PROJ ? (size_t)z * OUT_ELEMS : 0);
    const __nv_bfloat16* Xlo = g_Xlo + (PROJ ? (size_t)z * OUT_ELEMS : 0);
    const __nv_bfloat16* Whi = g_Whi + (size_t)z * HD * HD;
    const __nv_bfloat16* Wlo = g_Wlo + (size_t)z * HD * HD;
    const float* bias = PROJ ? ((z == 0) ? b0 : (z == 1) ? b1 : b2) : b0;

    float acc[16][4];
#pragma unroll
    for (int i = 0; i < 16; i++)
#pragma unroll
        for (int j = 0; j < 4; j++) acc[i][j] = 0.f;

    const int r0 = tid >> 2, c0 = tid & 3;
    const int r1 = r0 + 64;

    auto cp_stage = [&](int st, int k0) {
        uint32_t d = sb + st * GSTAGE;
        CP16(d + 0*GMAT + r0*GSTR + c0*16, Xhi + (size_t)(m0 + r0)*HD + k0 + c0*8);
        CP16(d + 0*GMAT + r1*GSTR + c0*16, Xhi + (size_t)(m0 + r1)*HD + k0 + c0*8);
        CP16(d + 1*GMAT + r0*GSTR + c0*16, Xlo + (size_t)(m0 + r0)*HD + k0 + c0*8);
        CP16(d + 1*GMAT + r1*GSTR + c0*16, Xlo + (size_t)(m0 + r1)*HD + k0 + c0*8);
        CP16(d + 2*GMAT + r0*GSTR + c0*16, Whi + (size_t)(n0 + r0)*HD + k0 + c0*8);
        CP16(d + 2*GMAT + r1*GSTR + c0*16, Whi + (size_t)(n0 + r1)*HD + k0 + c0*8);
        CP16(d + 3*GMAT + r0*GSTR + c0*16, Wlo + (size_t)(n0 + r0)*HD + k0 + c0*8);
        CP16(d + 3*GMAT + r1*GSTR + c0*16, Wlo + (size_t)(n0 + r1)*HD + k0 + c0*8);
        CP_COMMIT();
    };

    const int lrow = lane & 15;
    const int lcol = (lane >> 4) * 16;

    cp_stage(0, 0);
    cp_stage(1, 32);

    int s = 0;
#pragma unroll 1
    for (int c = 0; c < 32; ++c) {
        if (c < 31) { CP_WAIT1(); } else { CP_WAIT0(); }
        __syncthreads();
        if (c + 2 < 32) cp_stage((s + 2) % 3, (c + 2) * 32);   // single-sync pipeline

        const uint32_t stA = sb + s * GSTAGE;
        const uint32_t stB = stA + 2 * GMAT;
#pragma unroll
        for (int ks = 0; ks < 2; ++ks) {
            uint32_t ah[2][4], al[2][4], bh[4][4], bl[4][4];
#pragma unroll
            for (int fm = 0; fm < 2; ++fm) {
                uint32_t ra = stA + (wm*32 + fm*16 + lrow)*GSTR + lcol + ks*32;
                ldmx4(ah[fm], ra);
                ldmx4(al[fm], ra + GMAT);
            }
#pragma unroll
            for (int g = 0; g < 4; ++g) {
                uint32_t rb = stB + (wn*64 + g*16 + lrow)*GSTR + lcol + ks*32;
                ldmx4(bh[g], rb);
                ldmx4(bl[g], rb + GMAT);
            }
#pragma unroll
            for (int fm = 0; fm < 2; ++fm)
#pragma unroll
                for (int fn = 0; fn < 8; ++fn) {
                    const int g = fn >> 1, sel = fn & 1;
                    float* cc = acc[fm*8 + fn];
                    mma_bf16(cc, ah[fm], bh[g][sel], bh[g][sel+2]);
                    mma_bf16(cc, ah[fm], bl[g][sel], bl[g][sel+2]);
                    mma_bf16(cc, al[fm], bh[g][sel], bh[g][sel+2]);
                }
        }
        s = (s + 1) % 3;
    }

    // epilogue
#pragma unroll
    for (int fm = 0; fm < 2; ++fm)
#pragma unroll
        for (int fn = 0; fn < 8; ++fn) {
            const float* cc = acc[fm*8 + fn];
            const int m = m0 + wm*32 + fm*16 + (lane >> 2);
            const int n = n0 + wn*64 + fn*8 + (lane & 3)*2;
            float2 bv = *(const float2*)&bias[n];
            float v0 = cc[0] + bv.x, v1 = cc[1] + bv.y;    // row m
            float v2 = cc[2] + bv.x, v3 = cc[3] + bv.y;    // row m+8
            if (!PROJ) {
                *(float2*)&outp[(size_t)m * HD + n]       = make_float2(v0, v1);
                *(float2*)&outp[(size_t)(m + 8) * HD + n] = make_float2(v2, v3);
            } else {
                const int b = m >> 10, sq = m & 1023;
                const int h = n >> 6,  d  = n & 63;
                size_t o0 = (((size_t)(b*HH + h))*HS + sq    )*HDK + d;
                size_t o1 = (((size_t)(b*HH + h))*HS + sq + 8)*HDK + d;
                if (z == 2) {
                    *(float2*)&g_Vf[o0] = make_float2(v0, v1);
                    *(float2*)&g_Vf[o1] = make_float2(v2, v3);
                } else {
                    if (z == 0) { v0 *= 0.125f; v1 *= 0.125f; v2 *= 0.125f; v3 *= 0.125f; }
                    uint32_t h0, l0, h1, l1;
                    split2(v0, v1, h0, l0);
                    split2(v2, v3, h1, l1);
                    __nv_bfloat16* Yhi = (z == 0) ? g_Qhi : g_Khi;
                    __nv_bfloat16* Ylo = (z == 0) ? g_Qlo : g_Klo;
                    *(uint32_t*)&Yhi[o0] = h0; *(uint32_t*)&Ylo[o0] = l0;
                    *(uint32_t*)&Yhi[o1] = h1; *(uint32_t*)&Ylo[o1] = l1;
                }
            }
        }
}

// ---------------------------------------------------------------------------
// Fused attention: QK^T (cp.async 2-stage) -> softmax (attn streamed out)
// -> P@V (VT cp.async 2-stage through reused buffers) -> ctx split bf16.
// CTA = (32 q rows, bh), 256 threads.
// ---------------------------------------------------------------------------
#define SSTR 1032
#define SS_BYTES (32*SSTR*4)            // 132096
// phase 1 overlay
#define OFF_Q SS_BYTES
#define QSTR 144
#define SQ_MAT (32*QSTR)                // 4608
#define OFF_K (OFF_Q + 2*SQ_MAT)        // 141312
#define KSTR 144
#define SK_MAT (128*KSTR)               // 18432
#define KSTG (2*SK_MAT)                 // 36864
// phase 3 overlay (same region)
#define OFF_P SS_BYTES                  // 132096
#define PSTR 272
#define SP_MAT (32*PSTR)                // 8704
#define OFF_VT (OFF_P + 2*SP_MAT)       // 149504
#define VSTR 272
#define SVT_MAT (64*VSTR)               // 17408
#define VSTG (2*SVT_MAT)                // 34816
#define ATTN_SMEM (OFF_VT + 2*VSTG)     // 219136

__global__ __launch_bounds__(256, 1)
void attn_fused(float* __restrict__ attn_out)
{
    extern __shared__ char sm[];
    const uint32_t sb = smem_u32(sm);
    float* Ss = (float*)sm;

    const int tid = threadIdx.x;
    const int wid = tid >> 5, lane = tid & 31;
    const int bh = blockIdx.y;
    const int q0 = blockIdx.x * 32;

    const __nv_bfloat16* Qhi = g_Qhi + (size_t)bh * HS * HDK;
    const __nv_bfloat16* Qlo = g_Qlo + (size_t)bh * HS * HDK;
    const __nv_bfloat16* Khi = g_Khi + (size_t)bh * HS * HDK;
    const __nv_bfloat16* Klo = g_Klo + (size_t)bh * HS * HDK;
    const __nv_bfloat16* VThi = g_VThi + (size_t)bh * HDK * HS;
    const __nv_bfloat16* VTlo = g_VTlo + (size_t)bh * HDK * HS;

    const int lrow = lane & 15;
    const int lcol = (lane >> 4) * 16;

    // Q tile 32x64 hi/lo
#pragma unroll
    for (int i = 0; i < 2; ++i) {
        int g = tid + i * 256;
        int mat = g >> 8, gg = g & 255;
        int r = gg >> 3, cg = gg & 7;
        const __nv_bfloat16* src = (mat ? Qlo : Qhi) + (size_t)(q0 + r)*HDK + cg*8;
        *(uint4*)(sm + OFF_Q + mat*SQ_MAT + r*QSTR + cg*16) = *(const uint4*)src;
    }

    auto cp_K = [&](int st, int kt) {
        uint32_t d = sb + OFF_K + st * KSTG;
#pragma unroll
        for (int i = 0; i < 8; ++i) {
            int g = tid + i * 256;
            int mat = g >> 10, gg = g & 1023;
            int r = gg >> 3, cg = gg & 7;
            const __nv_bfloat16* src = (mat ? Klo : Khi) + (size_t)(kt*128 + r)*HDK + cg*8;
            CP16(d + mat*SK_MAT + r*KSTR + cg*16, src);
        }
        CP_COMMIT();
    };
    auto cp_VT = [&](int st, int kt) {
        uint32_t d = sb + OFF_VT + st * VSTG;
#pragma unroll
        for (int i = 0; i < 8; ++i) {
            int g = tid + i * 256;
            int mat = g >> 10, gg = g & 1023;
            int r = gg >> 4, cg = gg & 15;
            const __nv_bfloat16* src = (mat ? VTlo : VThi) + (size_t)r*HS + kt*128 + cg*8;
            CP16(d + mat*SVT_MAT + r*VSTR + cg*16, src);
        }
        CP_COMMIT();
    };

    cp_K(0, 0);

    // ---- Phase 1: scores ----
    const int wm = wid & 1, wn = wid >> 1;   // wm: 16 q rows, wn: 32 keys
#pragma unroll 1
    for (int kt = 0; kt < 8; ++kt) {
        const int s = kt & 1;
        if (kt < 7) cp_K(s ^ 1, kt + 1);
        if (kt < 7) { CP_WAIT1(); } else { CP_WAIT0(); }
        __syncthreads();

        float acc[4][4];
#pragma unroll
        for (int i = 0; i < 4; i++)
#pragma unroll
            for (int j = 0; j < 4; j++) acc[i][j] = 0.f;

        const uint32_t stK = sb + OFF_K + s * KSTG;
#pragma unroll
        for (int ks = 0; ks < 4; ++ks) {
            uint32_t ah[4], al[4], bh[2][4], bl[2][4];
            uint32_t ra = sb + OFF_Q + (wm*16 + lrow)*QSTR + lcol + ks*32;
            ldmx4(ah, ra);
            ldmx4(al, ra + SQ_MAT);
#pragma unroll
            for (int g = 0; g < 2; ++g) {
                uint32_t rb = stK + (wn*32 + g*16 + lrow)*KSTR + lcol + ks*32;
                ldmx4(bh[g], rb);
                ldmx4(bl[g], rb + SK_MAT);
            }
#pragma unroll
            for (int fn = 0; fn < 4; ++fn) {
                const int g = fn >> 1, sel = fn & 1;
                mma_bf16(acc[fn], ah, bh[g][sel], bh[g][sel+2]);
                mma_bf16(acc[fn], ah, bl[g][sel], bl[g][sel+2]);
                mma_bf16(acc[fn], al, bh[g][sel], bh[g][sel+2]);
            }
        }
#pragma unroll
        for (int fn = 0; fn < 4; ++fn) {
            int row = wm*16 + (lane >> 2);
            int col = kt*128 + wn*32 + fn*8 + (lane & 3)*2;
            *(float2*)&Ss[(size_t)row * SSTR + col]       = make_float2(acc[fn][0], acc[fn][1]);
            *(float2*)&Ss[(size_t)(row + 8) * SSTR + col] = make_float2(acc[fn][2], acc[fn][3]);
        }
        __syncthreads();
    }

    // prefetch first VT tile (overlaps softmax; K reads all done)
    cp_VT(0, 0);

    // ---- Phase 2: softmax (8 threads/row); stream attn out ----
    {
        const int row = tid >> 3;
        const int t8  = tid & 7;
        float* srow = Ss + (size_t)row * SSTR;

        float mx = -1e30f;
#pragma unroll
        for (int i = 0; i < 32; i++) {
            float4 v = *(const float4*)&srow[t8*4 + i*32];
            mx = fmaxf(mx, fmaxf(fmaxf(v.x, v.y), fmaxf(v.z, v.w)));
        }
#pragma unroll
        for (int o = 4; o >= 1; o >>= 1)
            mx = fmaxf(mx, __shfl_xor_sync(0xffffffffu, mx, o));

        float sum = 0.f;
#pragma unroll
        for (int i = 0; i < 32; i++) {
            float4 v = *(float4*)&srow[t8*4 + i*32];
            v.x = __expf(v.x - mx); v.y = __expf(v.y - mx);
            v.z = __expf(v.z - mx); v.w = __expf(v.w - mx);
            sum += v.x + v.y + v.z + v.w;
            *(float4*)&srow[t8*4 + i*32] = v;
        }
#pragma unroll
        for (int o = 4; o >= 1; o >>= 1)
            sum += __shfl_xor_sync(0xffffffffu, sum, o);
        float inv = 1.f / sum;

        float* arow = attn_out + ((size_t)bh * HS + q0 + row) * HS;
#pragma unroll
        for (int i = 0; i < 32; i++) {
            float4 v = *(float4*)&srow[t8*4 + i*32];
            v.x *= inv; v.y *= inv; v.z *= inv; v.w *= inv;
            *(float4*)&srow[t8*4 + i*32] = v;
            __stcs((float4*)&arow[t8*4 + i*32], v);       // streaming store
        }
    }
    __syncthreads();

    // ---- Phase 3: ctx = P @ V ----
    const int wn3 = wid >> 1;                  // d group: wn3*16
    float acc2[2][4];
#pragma unroll
    for (int i = 0; i < 2; i++)
#pragma unroll
        for (int j = 0; j < 4; j++) acc2[i][j] = 0.f;

#pragma unroll 1
    for (int kt = 0; kt < 8; ++kt) {
        const int s = kt & 1;
        // convert P chunk 32x128 -> bf16 hi/lo (8 float2 per thread)
#pragma unroll
        for (int i = 0; i < 8; ++i) {
            int p = tid + i*256;
            int row = p >> 6, cp = p & 63;
            float2 v = *(const float2*)&Ss[(size_t)row * SSTR + kt*128 + cp*2];
            uint32_t h, l;
            split2(v.x, v.y, h, l);
            *(uint32_t*)(sm + OFF_P + row*PSTR + cp*4) = h;
            *(uint32_t*)(sm + OFF_P + SP_MAT + row*PSTR + cp*4) = l;
        }
        if (kt < 7) cp_VT(s ^ 1, kt + 1);
        if (kt < 7) { CP_WAIT1(); } else { CP_WAIT0(); }
        __syncthreads();

        const uint32_t stVT = sb + OFF_VT + s * VSTG;
#pragma unroll
        for (int ks = 0; ks < 8; ++ks) {
            uint32_t ah[4], al[4], bh[4], bl[4];
            uint32_t ra = sb + OFF_P + (wm*16 + lrow)*PSTR + lcol + ks*32;
            ldmx4(ah, ra);
            ldmx4(al, ra + SP_MAT);
            uint32_t rb = stVT + (wn3*16 + lrow)*VSTR + lcol + ks*32;
            ldmx4(bh, rb);
            ldmx4(bl, rb + SVT_MAT);
#pragma unroll
            for (int fn = 0; fn < 2; ++fn) {
                mma_bf16(acc2[fn], ah, bh[fn], bh[fn+2]);
                mma_bf16(acc2[fn], ah, bl[fn], bl[fn+2]);
                mma_bf16(acc2[fn], al, bh[fn], bh[fn+2]);
            }
        }
        __syncthreads();
    }

    // epilogue: ctx split -> g_Xhi/g_Xlo slot0 row-major [4096][1024]
    {
        const int b = bh >> 4, h = bh & 15;
#pragma unroll
        for (int fn = 0; fn < 2; ++fn) {
            int s  = q0 + wm*16 + (lane >> 2);
            int cl = h*64 + wn3*16 + fn*8 + (lane & 3)*2;
            size_t o0 = (size_t)(b*HS + s)     * HD + cl;
            size_t o1 = (size_t)(b*HS + s + 8) * HD + cl;
            uint32_t h0, l0, h1, l1;
            split2(acc2[fn][0], acc2[fn][1], h0, l0);
            split2(acc2[fn][2], acc2[fn][3], h1, l1);
            *(uint32_t*)&g_Xhi[o0] = h0; *(uint32_t*)&g_Xlo[o0] = l0;
            *(uint32_t*)&g_Xhi[o1] = h1; *(uint32_t*)&g_Xlo[o1] = l1;
        }
    }
}

// ---------------------------------------------------------------------------
extern "C" void kernel_launch(void* const* d_in, const int* in_sizes, int n_in,
                              void* d_out, int out_size)
{
    const float* q  = (const float*)d_in[0];
    const float* k  = (const float*)d_in[1];
    const float* v  = (const float*)d_in[2];
    const float* Wq = (const float*)d_in[3];
    const float* bq = (const float*)d_in[4];
    const float* Wk = (const float*)d_in[5];
    const float* bk = (const float*)d_in[6];
    const float* Wv = (const float*)d_in[7];
    const float* bv = (const float*)d_in[8];
    const float* Wo = (const float*)d_in[9];
    const float* bo = (const float*)d_in[10];

    float* out  = (float*)d_out;
    float* attn = out + OUT_ELEMS;

    cudaFuncSetAttribute(gemm5<true>,  cudaFuncAttributeMaxDynamicSharedMemorySize, GT_SMEM);
    cudaFuncSetAttribute(gemm5<false>, cudaFuncAttributeMaxDynamicSharedMemorySize, GT_SMEM);
    cudaFuncSetAttribute(attn_fused, cudaFuncAttributeMaxDynamicSharedMemorySize, ATTN_SMEM);

    // 1. split q,k,v -> bf16 hi/lo
    splitQKV_k<<<3 * N4 / 256, 256>>>((const float4*)q, (const float4*)k,
                                      (const float4*)v);
    // 2. transpose+split all 4 weights
    wT4_k<<<dim3(HD/32, HD/32, 4), dim3(32, 8)>>>(Wq, Wk, Wv, Wo);
    // 3. Q,K,V projections in one launch
    gemm5<true><<<dim3(HD/128, MTOT/128, 3), 256, GT_SMEM>>>(bq, bk, bv, nullptr);
    // 4. V -> V^T split
    vT_split_k<<<dim3(64, NBH), dim3(32, 8)>>>();
    // 5. fused attention: scores + softmax + attn write + P@V -> ctx split
    attn_fused<<<dim3(HS/32, NBH), 256, ATTN_SMEM>>>(attn);
    // 6. out = ctx @ Wo + bo
    gemm5<false><<<dim3(HD/128, MTOT/128), 256, GT_SMEM>>>(bo, nullptr, nullptr, out);
}

// round 6
// speedup vs baseline: 1.0776x; 1.0776x over previous
#include <cuda_runtime.h>
#include <cstdint>

// Problem constants
#define HB   4
#define HS   1024
#define HD   1024
#define HH   16
#define HDK  64
#define MTOT (HB*HS)          // 4096
#define NBH  (HB*HH)          // 64
#define OUT_ELEMS (MTOT*HD)   // 4194304

// Scratch (allocation-free device globals) — all tf32-converted fp32 bits
__device__ float g_X[3*MTOT*HD];     // cvt inputs q,k,v (A); slot0 reused for ctx
__device__ float g_W[4*HD*HD];       // W^T [n][k], k8-pair-interleaved (B)
__device__ float g_Q[NBH*HS*HDK];    // [bh][s][d] row-major, pre-scaled (A)
__device__ float g_K[NBH*HS*HDK];    // [bh][key][d], d8-pair-interleaved (B)
__device__ float g_Vf[NBH*HS*HDK];   // [bh][s][d] plain fp32
__device__ float g_VT[NBH*HDK*HS];   // [bh][d][s], s8-pair-interleaved (B)

// ---------------------------------------------------------------------------
// helpers
// ---------------------------------------------------------------------------
__device__ __forceinline__ uint32_t smem_u32(const void* p) {
    uint32_t a;
    asm("{ .reg .u64 t; cvta.to.shared.u64 t, %1; cvt.u32.u64 %0, t; }"
        : "=r"(a) : "l"(p));
    return a;
}
__device__ __forceinline__ uint32_t cvt_tf32(float f) {
    uint32_t o;
    asm("cvt.rna.tf32.f32 %0, %1;" : "=r"(o) : "f"(f));
    return o;
}
__device__ __forceinline__ uint32_t lds32(uint32_t a) {
    uint32_t v;
    asm volatile("ld.shared.b32 %0, [%1];" : "=r"(v) : "r"(a));
    return v;
}
__device__ __forceinline__ void lds64(uint32_t& x, uint32_t& y, uint32_t a) {
    asm volatile("ld.shared.v2.b32 {%0,%1}, [%2];" : "=r"(x), "=r"(y) : "r"(a));
}
__device__ __forceinline__ void mma_tf32(float* c, const uint32_t* a,
                                         uint32_t b0, uint32_t b1) {
    asm volatile(
        "mma.sync.aligned.m16n8k8.row.col.f32.tf32.tf32.f32 "
        "{%0,%1,%2,%3}, {%4,%5,%6,%7}, {%8,%9}, {%0,%1,%2,%3};"
        : "+f"(c[0]), "+f"(c[1]), "+f"(c[2]), "+f"(c[3])
        : "r"(a[0]), "r"(a[1]), "r"(a[2]), "r"(a[3]), "r"(b0), "r"(b1));
}
// k8 pair-interleave: storage pos of k within its 8-group (k,k+4 adjacent)
__device__ __forceinline__ int kperm8(int k) {      // k in 0..7
    return ((k & 3) << 1) | ((k >> 2) & 1);
}
#define CP16(dst, src) asm volatile("cp.async.cg.shared.global [%0], [%1], 16;" :: "r"(dst), "l"(src))
#define CP_COMMIT()    asm volatile("cp.async.commit_group;" ::: "memory")
#define CP_WAIT1()     asm volatile("cp.async.wait_group 1;" ::: "memory")
#define CP_WAIT0()     asm volatile("cp.async.wait_group 0;" ::: "memory")

// ---------------------------------------------------------------------------
// q,k,v fp32 -> tf32-cvt fp32 into g_X, one launch
// ---------------------------------------------------------------------------
#define N4 (OUT_ELEMS/4)
__global__ __launch_bounds__(256)
void repackQKV_k(const float4* __restrict__ q, const float4* __restrict__ k,
                 const float4* __restrict__ v)
{
    int i = blockIdx.x * 256 + threadIdx.x;          // 0 .. 3*N4
    int z = i / N4, j = i - z * N4;
    const float4* src = (z == 0) ? q : (z == 1) ? k : v;
    float4 val = src[j];
    uint4 o;
    o.x = cvt_tf32(val.x); o.y = cvt_tf32(val.y);
    o.z = cvt_tf32(val.z); o.w = cvt_tf32(val.w);
    ((uint4*)(g_X + (size_t)z * OUT_ELEMS))[j] = o;
}

// ---------------------------------------------------------------------------
// All 4 weights: W[k][n] fp32 -> W^T [n][k] tf32-cvt + k8 pair interleave
// ---------------------------------------------------------------------------
__global__ __launch_bounds__(256)
void wT4_k(const float* __restrict__ Wq, const float* __restrict__ Wk,
           const float* __restrict__ Wv, const float* __restrict__ Wo)
{
    __shared__ float t[32][33];
    const int z = blockIdx.z;
    const float* W = (z == 0) ? Wq : (z == 1) ? Wk : (z == 2) ? Wv : Wo;
    uint32_t* dst = (uint32_t*)(g_W + (size_t)z * HD * HD);
    int k0 = blockIdx.y * 32, n0 = blockIdx.x * 32;
    int tx = threadIdx.x, ty = threadIdx.y;   // (32, 8)
#pragma unroll
    for (int j = 0; j < 32; j += 8)
        t[ty + j][tx] = W[(size_t)(k0 + ty + j) * HD + n0 + tx];
    __syncthreads();
    int kk = k0 + tx;
    int kp = (kk & ~7) | kperm8(kk & 7);
#pragma unroll
    for (int j = 0; j < 32; j += 8)
        dst[(size_t)(n0 + ty + j) * HD + kp] = cvt_tf32(t[tx][ty + j]);
}

// ---------------------------------------------------------------------------
// g_Vf [bh][s][d] -> g_VT [bh][d][s] tf32-cvt + s8 pair interleave
// ---------------------------------------------------------------------------
__global__ __launch_bounds__(256)
void vT_k()
{
    __shared__ float t[32][33];
    int bh = blockIdx.y;
    int s0 = (blockIdx.x & 31) * 32;
    int d0 = (blockIdx.x >> 5) * 32;
    int tx = threadIdx.x, ty = threadIdx.y;   // (32, 8)
    const float* V = g_Vf + (size_t)bh * HS * HDK;
#pragma unroll
    for (int j = 0; j < 32; j += 8)
        t[ty + j][tx] = V[(size_t)(s0 + ty + j) * HDK + d0 + tx];
    __syncthreads();
    uint32_t* dst = (uint32_t*)(g_VT + (size_t)bh * HDK * HS);
    int ss = s0 + tx;
    int sp = (ss & ~7) | kperm8(ss & 7);
#pragma unroll
    for (int j = 0; j < 32; j += 8)
        dst[(size_t)(d0 + ty + j) * HS + sp] = cvt_tf32(t[tx][ty + j]);
}

// ---------------------------------------------------------------------------
// Dense tf32 GEMM (BM=128,BN=128,BK=32), cp.async 3-stage, 1 MMA per k8.
// PROJ=true: blockIdx.z in {0,1,2} = Q/K/V with fused epilogues.
// PROJ=false: out = ctx @ Wo + bo, fp32 row-major.
// ---------------------------------------------------------------------------
#define GSTRB 144                    // 32 floats data + 16B pad
#define GMATB (128*GSTRB)            // 18432
#define GSTG  (2*GMATB)              // 36864 (A + B)
#define GT_SMEM (3*GSTG)             // 110592

template<bool PROJ>
__global__ __launch_bounds__(256, 1)
void gemm5(const float* __restrict__ b0, const float* __restrict__ b1,
           const float* __restrict__ b2, float* __restrict__ outp)
{
    extern __shared__ char sm[];
    const uint32_t sb = smem_u32(sm);
    const int z = PROJ ? blockIdx.z : 3;
    const int tid = threadIdx.x;
    const int wid = tid >> 5, lane = tid & 31;
    const int wm = wid & 3, wn = wid >> 2;
    const int m0 = blockIdx.y * 128, n0 = blockIdx.x * 128;

    const float* X = g_X + (PROJ ? (size_t)z * OUT_ELEMS : 0);
    const float* W = g_W + (size_t)z * HD * HD;
    const float* bias = PROJ ? ((z == 0) ? b0 : (z == 1) ? b1 : b2) : b0;

    float acc[16][4];
#pragma unroll
    for (int i = 0; i < 16; i++)
#pragma unroll
        for (int j = 0; j < 4; j++) acc[i][j] = 0.f;

    auto cp_stage = [&](int st, int k0) {
        uint32_t d = sb + st * GSTG;
#pragma unroll
        for (int t = 0; t < 4; ++t) {
            int i = tid + t * 256;          // 0..1023
            int r = i >> 3, c = i & 7;
            CP16(d + r*GSTRB + c*16,         X + (size_t)(m0 + r)*HD + k0 + c*4);
            CP16(d + GMATB + r*GSTRB + c*16, W + (size_t)(n0 + r)*HD + k0 + c*4);
        }
        CP_COMMIT();
    };

    const int arow = lane >> 2, acol = lane & 3;

    cp_stage(0, 0);
    cp_stage(1, 32);

    int s = 0;
#pragma unroll 1
    for (int c = 0; c < 32; ++c) {
        if (c < 31) { CP_WAIT1(); } else { CP_WAIT0(); }
        __syncthreads();
        if (c + 2 < 32) cp_stage((s + 2) % 3, (c + 2) * 32);

        const uint32_t stA = sb + s * GSTG;
        const uint32_t stB = stA + GMATB;
#pragma unroll
        for (int ks = 0; ks < 4; ++ks) {
            uint32_t a[2][4], b[8][2];
#pragma unroll
            for (int fm = 0; fm < 2; ++fm) {
                uint32_t ra = stA + (wm*32 + fm*16 + arow)*GSTRB + ks*32 + acol*4;
                a[fm][0] = lds32(ra);
                a[fm][1] = lds32(ra + 8*GSTRB);
                a[fm][2] = lds32(ra + 16);
                a[fm][3] = lds32(ra + 8*GSTRB + 16);
            }
#pragma unroll
            for (int g = 0; g < 8; ++g) {
                uint32_t rb = stB + (wn*64 + g*8 + arow)*GSTRB + ks*32 + acol*8;
                lds64(b[g][0], b[g][1], rb);
            }
#pragma unroll
            for (int fm = 0; fm < 2; ++fm)
#pragma unroll
                for (int g = 0; g < 8; ++g)
                    mma_tf32(acc[fm*8 + g], a[fm], b[g][0], b[g][1]);
        }
        s = (s + 1) % 3;
    }

    // epilogue
#pragma unroll
    for (int fm = 0; fm < 2; ++fm)
#pragma unroll
        for (int fn = 0; fn < 8; ++fn) {
            const float* cc = acc[fm*8 + fn];
            const int m = m0 + wm*32 + fm*16 + (lane >> 2);
            const int n = n0 + wn*64 + fn*8 + (lane & 3)*2;
            float2 bv = *(const float2*)&bias[n];
            float v0 = cc[0] + bv.x, v1 = cc[1] + bv.y;    // row m
            float v2 = cc[2] + bv.x, v3 = cc[3] + bv.y;    // row m+8
            if (!PROJ) {
                *(float2*)&outp[(size_t)m * HD + n]       = make_float2(v0, v1);
                *(float2*)&outp[(size_t)(m + 8) * HD + n] = make_float2(v2, v3);
            } else {
                const int b = m >> 10, sq = m & 1023;
                const int h = n >> 6,  d  = n & 63;
                size_t rbase = (((size_t)(b*HH + h))*HS + sq) * HDK;
                if (z == 2) {
                    *(float2*)&g_Vf[rbase + d]            = make_float2(v0, v1);
                    *(float2*)&g_Vf[rbase + 8*HDK + d]    = make_float2(v2, v3);
                } else if (z == 0) {
                    uint2 u0 = make_uint2(cvt_tf32(v0 * 0.125f), cvt_tf32(v1 * 0.125f));
                    uint2 u1 = make_uint2(cvt_tf32(v2 * 0.125f), cvt_tf32(v3 * 0.125f));
                    *(uint2*)&g_Q[rbase + d]         = u0;
                    *(uint2*)&g_Q[rbase + 8*HDK + d] = u1;
                } else {   // K: d8 pair-interleave
                    uint32_t* Kd = (uint32_t*)g_K;
                    int p0 = (d & ~7) | kperm8(d & 7);
                    int p1 = ((d+1) & ~7) | kperm8((d+1) & 7);
                    Kd[rbase + p0] = cvt_tf32(v0);
                    Kd[rbase + p1] = cvt_tf32(v1);
                    Kd[rbase + 8*HDK + p0] = cvt_tf32(v2);
                    Kd[rbase + 8*HDK + p1] = cvt_tf32(v3);
                }
            }
        }
}

// ---------------------------------------------------------------------------
// Fused attention (tf32): QK^T (2-stage cp.async K) -> softmax (attn streamed)
// -> P@V (2-stage cp.async VT) -> ctx tf32-cvt into g_X slot0.
// CTA = (32 q rows, bh), 256 threads.
// ---------------------------------------------------------------------------
#define SSTR 1032
#define SSB (32*SSTR*4)                 // 132096
#define OFF_Q SSB
#define QSTRB 272                       // 64 floats + 16B pad
#define OFF_K (OFF_Q + 32*QSTRB)        // 140800
#define KMATB (128*QSTRB)               // 34816 per stage
#define OFF_P SSB                       // overlay phase 3
#define PSTRB 528                       // 128 floats + 16B pad
#define OFF_VT (OFF_P + 32*PSTRB)       // 148992
#define VTMATB (64*PSTRB)               // 33792 per stage
#define ATTN_SMEM (OFF_VT + 2*VTMATB)   // 216576

__global__ __launch_bounds__(256, 1)
void attn_fused(float* __restrict__ attn_out)
{
    extern __shared__ char sm[];
    const uint32_t sb = smem_u32(sm);
    float* Ss = (float*)sm;

    const int tid = threadIdx.x;
    const int wid = tid >> 5, lane = tid & 31;
    const int bh = blockIdx.y;
    const int q0 = blockIdx.x * 32;
    const int arow = lane >> 2, acol = lane & 3;

    const float* Qg  = g_Q  + (size_t)bh * HS * HDK;
    const float* Kg  = g_K  + (size_t)bh * HS * HDK;
    const float* VTg = g_VT + (size_t)bh * HDK * HS;

    // Q tile 32x64 (2 chunks/thread)
#pragma unroll
    for (int t = 0; t < 2; ++t) {
        int i = tid + t * 256;
        int r = i >> 4, c = i & 15;
        *(uint4*)(sm + OFF_Q + r*QSTRB + c*16) =
            *(const uint4*)(Qg + (size_t)(q0 + r)*HDK + c*4);
    }

    auto cp_K = [&](int st, int kt) {
        uint32_t d = sb + OFF_K + st * KMATB;
#pragma unroll
        for (int t = 0; t < 8; ++t) {
            int i = tid + t * 256;
            int r = i >> 4, c = i & 15;
            CP16(d + r*QSTRB + c*16, Kg + (size_t)(kt*128 + r)*HDK + c*4);
        }
        CP_COMMIT();
    };
    auto cp_VT = [&](int st, int kt) {
        uint32_t d = sb + OFF_VT + st * VTMATB;
#pragma unroll
        for (int t = 0; t < 8; ++t) {
            int i = tid + t * 256;
            int r = i >> 5, c = i & 31;
            CP16(d + r*PSTRB + c*16, VTg + (size_t)r*HS + kt*128 + c*4);
        }
        CP_COMMIT();
    };

    cp_K(0, 0);

    // ---- Phase 1: scores ----
    const int wm = wid & 1, wn = wid >> 1;   // wm: 16 q rows, wn: 32 keys
#pragma unroll 1
    for (int kt = 0; kt < 8; ++kt) {
        const int s = kt & 1;
        if (kt < 7) cp_K(s ^ 1, kt + 1);
        if (kt < 7) { CP_WAIT1(); } else { CP_WAIT0(); }
        __syncthreads();

        float acc[4][4];
#pragma unroll
        for (int i = 0; i < 4; i++)
#pragma unroll
            for (int j = 0; j < 4; j++) acc[i][j] = 0.f;

        const uint32_t stK = sb + OFF_K + s * KMATB;
#pragma unroll
        for (int ks = 0; ks < 8; ++ks) {
            uint32_t a[4], b[4][2];
            uint32_t ra = sb + OFF_Q + (wm*16 + arow)*QSTRB + ks*32 + acol*4;
            a[0] = lds32(ra);
            a[1] = lds32(ra + 8*QSTRB);
            a[2] = lds32(ra + 16);
            a[3] = lds32(ra + 8*QSTRB + 16);
#pragma unroll
            for (int g = 0; g < 4; ++g) {
                uint32_t rb = stK + (wn*32 + g*8 + arow)*QSTRB + ks*32 + acol*8;
                lds64(b[g][0], b[g][1], rb);
            }
#pragma unroll
            for (int g = 0; g < 4; ++g)
                mma_tf32(acc[g], a, b[g][0], b[g][1]);
        }
#pragma unroll
        for (int fn = 0; fn < 4; ++fn) {
            int row = wm*16 + (lane >> 2);
            int col = kt*128 + wn*32 + fn*8 + (lane & 3)*2;
            *(float2*)&Ss[(size_t)row * SSTR + col]       = make_float2(acc[fn][0], acc[fn][1]);
            *(float2*)&Ss[(size_t)(row + 8) * SSTR + col] = make_float2(acc[fn][2], acc[fn][3]);
        }
        __syncthreads();
    }

    // prefetch first VT tile (K fully consumed; overlaps softmax)
    cp_VT(0, 0);

    // ---- Phase 2: softmax (8 threads/row); stream attn out ----
    {
        const int row = tid >> 3;
        const int t8  = tid & 7;
        float* srow = Ss + (size_t)row * SSTR;

        float mx = -1e30f;
#pragma unroll
        for (int i = 0; i < 32; i++) {
            float4 v = *(const float4*)&srow[t8*4 + i*32];
            mx = fmaxf(mx, fmaxf(fmaxf(v.x, v.y), fmaxf(v.z, v.w)));
        }
#pragma unroll
        for (int o = 4; o >= 1; o >>= 1)
            mx = fmaxf(mx, __shfl_xor_sync(0xffffffffu, mx, o));

        float sum = 0.f;
#pragma unroll
        for (int i = 0; i < 32; i++) {
            float4 v = *(float4*)&srow[t8*4 + i*32];
            v.x = __expf(v.x - mx); v.y = __expf(v.y - mx);
            v.z = __expf(v.z - mx); v.w = __expf(v.w - mx);
            sum += v.x + v.y + v.z + v.w;
            *(float4*)&srow[t8*4 + i*32] = v;
        }
#pragma unroll
        for (int o = 4; o >= 1; o >>= 1)
            sum += __shfl_xor_sync(0xffffffffu, sum, o);
        float inv = 1.f / sum;

        float* arow = attn_out + ((size_t)bh * HS + q0 + row) * HS;
#pragma unroll
        for (int i = 0; i < 32; i++) {
            float4 v = *(float4*)&srow[t8*4 + i*32];
            v.x *= inv; v.y *= inv; v.z *= inv; v.w *= inv;
            *(float4*)&srow[t8*4 + i*32] = v;
            __stcs((float4*)&arow[t8*4 + i*32], v);       // streaming store
        }
    }
    __syncthreads();

    // ---- Phase 3: ctx = P @ V ----
    const int wn3 = wid >> 1;                  // d group: wn3*16
    float acc2[2][4];
#pragma unroll
    for (int i = 0; i < 2; i++)
#pragma unroll
        for (int j = 0; j < 4; j++) acc2[i][j] = 0.f;

#pragma unroll 1
    for (int kt = 0; kt < 8; ++kt) {
        const int s = kt & 1;
        // P chunk 32x128 -> tf32 cvt into sP (8 float2 per thread)
#pragma unroll
        for (int i = 0; i < 8; ++i) {
            int p = tid + i*256;
            int row = p >> 6, cp = p & 63;
            float2 v = *(const float2*)&Ss[(size_t)row * SSTR + kt*128 + cp*2];
            uint2 u = make_uint2(cvt_tf32(v.x), cvt_tf32(v.y));
            *(uint2*)(sm + OFF_P + row*PSTRB + cp*8) = u;
        }
        if (kt < 7) cp_VT(s ^ 1, kt + 1);
        if (kt < 7) { CP_WAIT1(); } else { CP_WAIT0(); }
        __syncthreads();

        const uint32_t stVT = sb + OFF_VT + s * VTMATB;
#pragma unroll
        for (int ks = 0; ks < 16; ++ks) {
            uint32_t a[4], b[2][2];
            uint32_t ra = sb + OFF_P + (wm*16 + arow)*PSTRB + ks*32 + acol*4;
            a[0] = lds32(ra);
            a[1] = lds32(ra + 8*PSTRB);
            a[2] = lds32(ra + 16);
            a[3] = lds32(ra + 8*PSTRB + 16);
#pragma unroll
            for (int g = 0; g < 2; ++g) {
                uint32_t rb = stVT + (wn3*16 + g*8 + arow)*PSTRB + ks*32 + acol*8;
                lds64(b[g][0], b[g][1], rb);
            }
#pragma unroll
            for (int g = 0; g < 2; ++g)
                mma_tf32(acc2[g], a, b[g][0], b[g][1]);
        }
        __syncthreads();
    }

    // epilogue: ctx tf32-cvt -> g_X slot0 row-major [4096][1024]
    {
        const int b = bh >> 4, h = bh & 15;
#pragma unroll
        for (int fn = 0; fn < 2; ++fn) {
            int s  = q0 + wm*16 + (lane >> 2);
            int cl = h*64 + wn3*16 + fn*8 + (lane & 3)*2;
            size_t o0 = (size_t)(b*HS + s)     * HD + cl;
            size_t o1 = (size_t)(b*HS + s + 8) * HD + cl;
            uint2 u0 = make_uint2(cvt_tf32(acc2[fn][0]), cvt_tf32(acc2[fn][1]));
            uint2 u1 = make_uint2(cvt_tf32(acc2[fn][2]), cvt_tf32(acc2[fn][3]));
            *(uint2*)&g_X[o0] = u0;
            *(uint2*)&g_X[o1] = u1;
        }
    }
}

// ---------------------------------------------------------------------------
extern "C" void kernel_launch(void* const* d_in, const int* in_sizes, int n_in,
                              void* d_out, int out_size)
{
    const float* q  = (const float*)d_in[0];
    const float* k  = (const float*)d_in[1];
    const float* v  = (const float*)d_in[2];
    const float* Wq = (const float*)d_in[3];
    const float* bq = (const float*)d_in[4];
    const float* Wk = (const float*)d_in[5];
    const float* bk = (const float*)d_in[6];
    const float* Wv = (const float*)d_in[7];
    const float* bv = (const float*)d_in[8];
    const float* Wo = (const float*)d_in[9];
    const float* bo = (const float*)d_in[10];

    float* out  = (float*)d_out;
    float* attn = out + OUT_ELEMS;

    cudaFuncSetAttribute(gemm5<true>,  cudaFuncAttributeMaxDynamicSharedMemorySize, GT_SMEM);
    cudaFuncSetAttribute(gemm5<false>, cudaFuncAttributeMaxDynamicSharedMemorySize, GT_SMEM);
    cudaFuncSetAttribute(attn_fused, cudaFuncAttributeMaxDynamicSharedMemorySize, ATTN_SMEM);

    // 1. cvt q,k,v -> g_X
    repackQKV_k<<<3 * N4 / 256, 256>>>((const float4*)q, (const float4*)k,
                                       (const float4*)v);
    // 2. transpose+cvt+interleave all 4 weights
    wT4_k<<<dim3(HD/32, HD/32, 4), dim3(32, 8)>>>(Wq, Wk, Wv, Wo);
    // 3. Q,K,V projections in one launch
    gemm5<true><<<dim3(HD/128, MTOT/128, 3), 256, GT_SMEM>>>(bq, bk, bv, nullptr);
    // 4. V -> V^T cvt+interleave
    vT_k<<<dim3(64, NBH), dim3(32, 8)>>>();
    // 5. fused attention: scores + softmax + attn write + P@V -> ctx
    attn_fused<<<dim3(HS/32, NBH), 256, ATTN_SMEM>>>(attn);
    // 6. out = ctx @ Wo + bo
    gemm5<false><<<dim3(HD/128, MTOT/128), 256, GT_SMEM>>>(bo, nullptr, nullptr, out);
}

// round 7
// speedup vs baseline: 1.2076x; 1.1207x over previous
#include <cuda_runtime.h>
#include <cstdint>

// Problem constants
#define HB   4
#define HS   1024
#define HD   1024
#define HH   16
#define HDK  64
#define MTOT (HB*HS)          // 4096
#define NBH  (HB*HH)          // 64
#define OUT_ELEMS (MTOT*HD)   // 4194304

// Scratch (allocation-free device globals) — all tf32-converted fp32 bits
__device__ float g_X[3*MTOT*HD];     // cvt inputs q,k,v (A); slot0 reused for ctx
__device__ float g_W[4*HD*HD];       // W^T [n][k] (B)
__device__ float g_Q[NBH*HS*HDK];    // [bh][s][d] row-major, pre-scaled (A)
__device__ float g_K[NBH*HS*HDK];    // [bh][key][d] (B)
__device__ float g_Vf[NBH*HS*HDK];   // [bh][s][d] plain fp32
__device__ float g_VT[NBH*HDK*HS];   // [bh][d][s] (B)

// ---------------------------------------------------------------------------
// helpers
// ---------------------------------------------------------------------------
__device__ __forceinline__ uint32_t smem_u32(const void* p) {
    uint32_t a;
    asm("{ .reg .u64 t; cvta.to.shared.u64 t, %1; cvt.u32.u64 %0, t; }"
        : "=r"(a) : "l"(p));
    return a;
}
__device__ __forceinline__ uint32_t cvt_tf32(float f) {
    uint32_t o;
    asm("cvt.rna.tf32.f32 %0, %1;" : "=r"(o) : "f"(f));
    return o;
}
__device__ __forceinline__ void ldmx4(uint32_t* r, uint32_t addr) {
    asm volatile("ldmatrix.sync.aligned.m8n8.x4.shared.b16 {%0,%1,%2,%3}, [%4];"
        : "=r"(r[0]), "=r"(r[1]), "=r"(r[2]), "=r"(r[3]) : "r"(addr));
}
// a = {a0,a1,a2,a3} with a0=(r,c) a1=(r+8,c) a2=(r,c+4) a3=(r+8,c+4)
__device__ __forceinline__ void mma_tf32(float* c, uint32_t a0, uint32_t a1,
                                         uint32_t a2, uint32_t a3,
                                         uint32_t b0, uint32_t b1) {
    asm volatile(
        "mma.sync.aligned.m16n8k8.row.col.f32.tf32.tf32.f32 "
        "{%0,%1,%2,%3}, {%4,%5,%6,%7}, {%8,%9}, {%0,%1,%2,%3};"
        : "+f"(c[0]), "+f"(c[1]), "+f"(c[2]), "+f"(c[3])
        : "r"(a0), "r"(a1), "r"(a2), "r"(a3), "r"(b0), "r"(b1));
}
#define CP16(dst, src) asm volatile("cp.async.cg.shared.global [%0], [%1], 16;" :: "r"(dst), "l"(src))
#define CP_COMMIT()    asm volatile("cp.async.commit_group;" ::: "memory")
#define CP_WAIT1()     asm volatile("cp.async.wait_group 1;" ::: "memory")
#define CP_WAIT0()     asm volatile("cp.async.wait_group 0;" ::: "memory")

// ---------------------------------------------------------------------------
// q,k,v fp32 -> tf32-cvt fp32 into g_X, one launch
// ---------------------------------------------------------------------------
#define N4 (OUT_ELEMS/4)
__global__ __launch_bounds__(256)
void repackQKV_k(const float4* __restrict__ q, const float4* __restrict__ k,
                 const float4* __restrict__ v)
{
    int i = blockIdx.x * 256 + threadIdx.x;          // 0 .. 3*N4
    int z = i / N4, j = i - z * N4;
    const float4* src = (z == 0) ? q : (z == 1) ? k : v;
    float4 val = src[j];
    uint4 o;
    o.x = cvt_tf32(val.x); o.y = cvt_tf32(val.y);
    o.z = cvt_tf32(val.z); o.w = cvt_tf32(val.w);
    ((uint4*)(g_X + (size_t)z * OUT_ELEMS))[j] = o;
}

// ---------------------------------------------------------------------------
// All 4 weights: W[k][n] fp32 -> W^T [n][k] tf32-cvt
// ---------------------------------------------------------------------------
__global__ __launch_bounds__(256)
void wT4_k(const float* __restrict__ Wq, const float* __restrict__ Wk,
           const float* __restrict__ Wv, const float* __restrict__ Wo)
{
    __shared__ float t[32][33];
    const int z = blockIdx.z;
    const float* W = (z == 0) ? Wq : (z == 1) ? Wk : (z == 2) ? Wv : Wo;
    uint32_t* dst = (uint32_t*)(g_W + (size_t)z * HD * HD);
    int k0 = blockIdx.y * 32, n0 = blockIdx.x * 32;
    int tx = threadIdx.x, ty = threadIdx.y;   // (32, 8)
#pragma unroll
    for (int j = 0; j < 32; j += 8)
        t[ty + j][tx] = W[(size_t)(k0 + ty + j) * HD + n0 + tx];
    __syncthreads();
#pragma unroll
    for (int j = 0; j < 32; j += 8)
        dst[(size_t)(n0 + ty + j) * HD + k0 + tx] = cvt_tf32(t[tx][ty + j]);
}

// ---------------------------------------------------------------------------
// g_Vf [bh][s][d] -> g_VT [bh][d][s] tf32-cvt
// ---------------------------------------------------------------------------
__global__ __launch_bounds__(256)
void vT_k()
{
    __shared__ float t[32][33];
    int bh = blockIdx.y;
    int s0 = (blockIdx.x & 31) * 32;
    int d0 = (blockIdx.x >> 5) * 32;
    int tx = threadIdx.x, ty = threadIdx.y;   // (32, 8)
    const float* V = g_Vf + (size_t)bh * HS * HDK;
#pragma unroll
    for (int j = 0; j < 32; j += 8)
        t[ty + j][tx] = V[(size_t)(s0 + ty + j) * HDK + d0 + tx];
    __syncthreads();
    uint32_t* dst = (uint32_t*)(g_VT + (size_t)bh * HDK * HS);
#pragma unroll
    for (int j = 0; j < 32; j += 8)
        dst[(size_t)(d0 + ty + j) * HS + s0 + tx] = cvt_tf32(t[tx][ty + j]);
}

// ---------------------------------------------------------------------------
// Dense tf32 GEMM (BM=128,BN=128,BK=32), cp.async 3-stage, ldmatrix frags.
// PROJ=true: blockIdx.z in {0,1,2} = Q/K/V with fused epilogues.
// PROJ=false: out = ctx @ Wo + bo, fp32 row-major.
// ---------------------------------------------------------------------------
#define GSTRB 144                    // 32 floats data + 16B pad (stride ≡ 4 mod 32 words)
#define GMATB (128*GSTRB)            // 18432
#define GSTG  (2*GMATB)              // 36864 (A + B)
#define GT_SMEM (3*GSTG)             // 110592

template<bool PROJ>
__global__ __launch_bounds__(256, 1)
void gemm5(const float* __restrict__ b0, const float* __restrict__ b1,
           const float* __restrict__ b2, float* __restrict__ outp)
{
    extern __shared__ char sm[];
    const uint32_t sb = smem_u32(sm);
    const int z = PROJ ? blockIdx.z : 3;
    const int tid = threadIdx.x;
    const int wid = tid >> 5, lane = tid & 31;
    const int wm = wid & 3, wn = wid >> 2;
    const int m0 = blockIdx.y * 128, n0 = blockIdx.x * 128;

    const float* X = g_X + (PROJ ? (size_t)z * OUT_ELEMS : 0);
    const float* W = g_W + (size_t)z * HD * HD;
    const float* bias = PROJ ? ((z == 0) ? b0 : (z == 1) ? b1 : b2) : b0;

    float acc[16][4];
#pragma unroll
    for (int i = 0; i < 16; i++)
#pragma unroll
        for (int j = 0; j < 4; j++) acc[i][j] = 0.f;

    auto cp_stage = [&](int st, int k0) {
        uint32_t d = sb + st * GSTG;
#pragma unroll
        for (int t = 0; t < 4; ++t) {
            int i = tid + t * 256;          // 0..1023
            int r = i >> 3, c = i & 7;
            CP16(d + r*GSTRB + c*16,         X + (size_t)(m0 + r)*HD + k0 + c*4);
            CP16(d + GMATB + r*GSTRB + c*16, W + (size_t)(n0 + r)*HD + k0 + c*4);
        }
        CP_COMMIT();
    };

    // ldmatrix address components (same formula for A and B x4 pairs)
    const int mrow = (lane & 7) | ((lane & 16) >> 1);   // 0..15
    const int mcol = (lane & 8) ? 16 : 0;               // byte offset

    cp_stage(0, 0);
    cp_stage(1, 32);

    int s = 0;
#pragma unroll 1
    for (int c = 0; c < 32; ++c) {
        if (c < 31) { CP_WAIT1(); } else { CP_WAIT0(); }
        __syncthreads();
        if (c + 2 < 32) cp_stage((s + 2) % 3, (c + 2) * 32);

        const uint32_t stA = sb + s * GSTG;
        const uint32_t stB = stA + GMATB;
#pragma unroll
        for (int ks = 0; ks < 4; ++ks) {
            uint32_t a[2][4], b[4][4];
#pragma unroll
            for (int fm = 0; fm < 2; ++fm)
                ldmx4(a[fm], stA + (wm*32 + fm*16 + mrow)*GSTRB + ks*32 + mcol);
#pragma unroll
            for (int gp = 0; gp < 4; ++gp)
                ldmx4(b[gp], stB + (wn*64 + gp*16 + mrow)*GSTRB + ks*32 + mcol);
#pragma unroll
            for (int fm = 0; fm < 2; ++fm)
#pragma unroll
                for (int g = 0; g < 8; ++g) {
                    const int gp = g >> 1, sel = (g & 1) * 2;
                    // ldmatrix regs: {a0, a2, a1, a3} -> reorder
                    mma_tf32(acc[fm*8 + g], a[fm][0], a[fm][2], a[fm][1], a[fm][3],
                             b[gp][sel], b[gp][sel + 1]);
                }
        }
        s = (s + 1) % 3;
    }

    // epilogue
#pragma unroll
    for (int fm = 0; fm < 2; ++fm)
#pragma unroll
        for (int fn = 0; fn < 8; ++fn) {
            const float* cc = acc[fm*8 + fn];
            const int m = m0 + wm*32 + fm*16 + (lane >> 2);
            const int n = n0 + wn*64 + fn*8 + (lane & 3)*2;
            float2 bv = *(const float2*)&bias[n];
            float v0 = cc[0] + bv.x, v1 = cc[1] + bv.y;    // row m
            float v2 = cc[2] + bv.x, v3 = cc[3] + bv.y;    // row m+8
            if (!PROJ) {
                *(float2*)&outp[(size_t)m * HD + n]       = make_float2(v0, v1);
                *(float2*)&outp[(size_t)(m + 8) * HD + n] = make_float2(v2, v3);
            } else {
                const int b = m >> 10, sq = m & 1023;
                const int h = n >> 6,  d  = n & 63;
                size_t rbase = (((size_t)(b*HH + h))*HS + sq) * HDK;
                if (z == 2) {
                    *(float2*)&g_Vf[rbase + d]            = make_float2(v0, v1);
                    *(float2*)&g_Vf[rbase + 8*HDK + d]    = make_float2(v2, v3);
                } else {
                    float sc = (z == 0) ? 0.125f : 1.0f;
                    float* Y = (z == 0) ? g_Q : g_K;
                    uint2 u0 = make_uint2(cvt_tf32(v0 * sc), cvt_tf32(v1 * sc));
                    uint2 u1 = make_uint2(cvt_tf32(v2 * sc), cvt_tf32(v3 * sc));
                    *(uint2*)&Y[rbase + d]         = u0;
                    *(uint2*)&Y[rbase + 8*HDK + d] = u1;
                }
            }
        }
}

// ---------------------------------------------------------------------------
// Fused attention (tf32, ldmatrix): QK^T -> softmax (attn streamed) -> P@V.
// CTA = (32 q rows, bh), 256 threads.
// ---------------------------------------------------------------------------
#define SSTR 1032
#define SSB (32*SSTR*4)                 // 132096
#define OFF_Q SSB
#define QSTRB 272                       // 64 floats + 16B pad (68 words ≡ 4 mod 32)
#define OFF_K (OFF_Q + 32*QSTRB)        // 140800
#define KMATB (128*QSTRB)               // 34816 per stage
#define OFF_P SSB                       // overlay phase 3
#define PSTRB 528                       // 128 floats + 16B pad (132 ≡ 4 mod 32)
#define OFF_VT (OFF_P + 32*PSTRB)       // 148992
#define VTMATB (64*PSTRB)               // 33792 per stage
#define ATTN_SMEM (OFF_VT + 2*VTMATB)   // 216576

__global__ __launch_bounds__(256, 1)
void attn_fused(float* __restrict__ attn_out)
{
    extern __shared__ char sm[];
    const uint32_t sb = smem_u32(sm);
    float* Ss = (float*)sm;

    const int tid = threadIdx.x;
    const int wid = tid >> 5, lane = tid & 31;
    const int bh = blockIdx.y;
    const int q0 = blockIdx.x * 32;
    const int mrow = (lane & 7) | ((lane & 16) >> 1);
    const int mcol = (lane & 8) ? 16 : 0;

    const float* Qg  = g_Q  + (size_t)bh * HS * HDK;
    const float* Kg  = g_K  + (size_t)bh * HS * HDK;
    const float* VTg = g_VT + (size_t)bh * HDK * HS;

    // Q tile 32x64 (2 chunks/thread)
#pragma unroll
    for (int t = 0; t < 2; ++t) {
        int i = tid + t * 256;
        int r = i >> 4, c = i & 15;
        *(uint4*)(sm + OFF_Q + r*QSTRB + c*16) =
            *(const uint4*)(Qg + (size_t)(q0 + r)*HDK + c*4);
    }

    auto cp_K = [&](int st, int kt) {
        uint32_t d = sb + OFF_K + st * KMATB;
#pragma unroll
        for (int t = 0; t < 8; ++t) {
            int i = tid + t * 256;
            int r = i >> 4, c = i & 15;
            CP16(d + r*QSTRB + c*16, Kg + (size_t)(kt*128 + r)*HDK + c*4);
        }
        CP_COMMIT();
    };
    auto cp_VT = [&](int st, int kt) {
        uint32_t d = sb + OFF_VT + st * VTMATB;
#pragma unroll
        for (int t = 0; t < 8; ++t) {
            int i = tid + t * 256;
            int r = i >> 5, c = i & 31;
            CP16(d + r*PSTRB + c*16, VTg + (size_t)r*HS + kt*128 + c*4);
        }
        CP_COMMIT();
    };

    cp_K(0, 0);

    // ---- Phase 1: scores ----
    const int wm = wid & 1, wn = wid >> 1;   // wm: 16 q rows, wn: 32 keys
#pragma unroll 1
    for (int kt = 0; kt < 8; ++kt) {
        const int s = kt & 1;
        if (kt < 7) cp_K(s ^ 1, kt + 1);
        if (kt < 7) { CP_WAIT1(); } else { CP_WAIT0(); }
        __syncthreads();

        float acc[4][4];
#pragma unroll
        for (int i = 0; i < 4; i++)
#pragma unroll
            for (int j = 0; j < 4; j++) acc[i][j] = 0.f;

        const uint32_t stK = sb + OFF_K + s * KMATB;
#pragma unroll
        for (int ks = 0; ks < 8; ++ks) {
            uint32_t a[4], b[2][4];
            ldmx4(a, sb + OFF_Q + (wm*16 + mrow)*QSTRB + ks*32 + mcol);
#pragma unroll
            for (int gp = 0; gp < 2; ++gp)
                ldmx4(b[gp], stK + (wn*32 + gp*16 + mrow)*QSTRB + ks*32 + mcol);
#pragma unroll
            for (int g = 0; g < 4; ++g) {
                const int gp = g >> 1, sel = (g & 1) * 2;
                mma_tf32(acc[g], a[0], a[2], a[1], a[3], b[gp][sel], b[gp][sel+1]);
            }
        }
#pragma unroll
        for (int fn = 0; fn < 4; ++fn) {
            int row = wm*16 + (lane >> 2);
            int col = kt*128 + wn*32 + fn*8 + (lane & 3)*2;
            *(float2*)&Ss[(size_t)row * SSTR + col]       = make_float2(acc[fn][0], acc[fn][1]);
            *(float2*)&Ss[(size_t)(row + 8) * SSTR + col] = make_float2(acc[fn][2], acc[fn][3]);
        }
        __syncthreads();
    }

    // prefetch first VT tile (K fully consumed; overlaps softmax)
    cp_VT(0, 0);

    // ---- Phase 2: softmax (8 threads/row); stream attn out ----
    {
        const int row = tid >> 3;
        const int t8  = tid & 7;
        float* srow = Ss + (size_t)row * SSTR;

        float mx = -1e30f;
#pragma unroll
        for (int i = 0; i < 32; i++) {
            float4 v = *(const float4*)&srow[t8*4 + i*32];
            mx = fmaxf(mx, fmaxf(fmaxf(v.x, v.y), fmaxf(v.z, v.w)));
        }
#pragma unroll
        for (int o = 4; o >= 1; o >>= 1)
            mx = fmaxf(mx, __shfl_xor_sync(0xffffffffu, mx, o));

        float sum = 0.f;
#pragma unroll
        for (int i = 0; i < 32; i++) {
            float4 v = *(float4*)&srow[t8*4 + i*32];
            v.x = __expf(v.x - mx); v.y = __expf(v.y - mx);
            v.z = __expf(v.z - mx); v.w = __expf(v.w - mx);
            sum += v.x + v.y + v.z + v.w;
            *(float4*)&srow[t8*4 + i*32] = v;
        }
#pragma unroll
        for (int o = 4; o >= 1; o >>= 1)
            sum += __shfl_xor_sync(0xffffffffu, sum, o);
        float inv = 1.f / sum;

        float* arow = attn_out + ((size_t)bh * HS + q0 + row) * HS;
#pragma unroll
        for (int i = 0; i < 32; i++) {
            float4 v = *(float4*)&srow[t8*4 + i*32];
            v.x *= inv; v.y *= inv; v.z *= inv; v.w *= inv;
            *(float4*)&srow[t8*4 + i*32] = v;
            __stcs((float4*)&arow[t8*4 + i*32], v);       // streaming store
        }
    }
    __syncthreads();

    // ---- Phase 3: ctx = P @ V ----
    const int wn3 = wid >> 1;                  // d group: wn3*16
    float acc2[2][4];
#pragma unroll
    for (int i = 0; i < 2; i++)
#pragma unroll
        for (int j = 0; j < 4; j++) acc2[i][j] = 0.f;

#pragma unroll 1
    for (int kt = 0; kt < 8; ++kt) {
        const int s = kt & 1;
        // P chunk 32x128 -> tf32 cvt into sP (8 float2 per thread)
#pragma unroll
        for (int i = 0; i < 8; ++i) {
            int p = tid + i*256;
            int row = p >> 6, cp = p & 63;
            float2 v = *(const float2*)&Ss[(size_t)row * SSTR + kt*128 + cp*2];
            uint2 u = make_uint2(cvt_tf32(v.x), cvt_tf32(v.y));
            *(uint2*)(sm + OFF_P + row*PSTRB + cp*8) = u;
        }
        if (kt < 7) cp_VT(s ^ 1, kt + 1);
        if (kt < 7) { CP_WAIT1(); } else { CP_WAIT0(); }
        __syncthreads();

        const uint32_t stVT = sb + OFF_VT + s * VTMATB;
#pragma unroll
        for (int ks = 0; ks < 16; ++ks) {
            uint32_t a[4], b[4];
            ldmx4(a, sb + OFF_P + (wm*16 + mrow)*PSTRB + ks*32 + mcol);
            ldmx4(b, stVT + (wn3*16 + mrow)*PSTRB + ks*32 + mcol);
#pragma unroll
            for (int g = 0; g < 2; ++g)
                mma_tf32(acc2[g], a[0], a[2], a[1], a[3], b[g*2], b[g*2+1]);
        }
        __syncthreads();
    }

    // epilogue: ctx tf32-cvt -> g_X slot0 row-major [4096][1024]
    {
        const int b = bh >> 4, h = bh & 15;
#pragma unroll
        for (int fn = 0; fn < 2; ++fn) {
            int s  = q0 + wm*16 + (lane >> 2);
            int cl = h*64 + wn3*16 + fn*8 + (lane & 3)*2;
            size_t o0 = (size_t)(b*HS + s)     * HD + cl;
            size_t o1 = (size_t)(b*HS + s + 8) * HD + cl;
            uint2 u0 = make_uint2(cvt_tf32(acc2[fn][0]), cvt_tf32(acc2[fn][1]));
            uint2 u1 = make_uint2(cvt_tf32(acc2[fn][2]), cvt_tf32(acc2[fn][3]));
            *(uint2*)&g_X[o0] = u0;
            *(uint2*)&g_X[o1] = u1;
        }
    }
}

// ---------------------------------------------------------------------------
extern "C" void kernel_launch(void* const* d_in, const int* in_sizes, int n_in,
                              void* d_out, int out_size)
{
    const float* q  = (const float*)d_in[0];
    const float* k  = (const float*)d_in[1];
    const float* v  = (const float*)d_in[2];
    const float* Wq = (const float*)d_in[3];
    const float* bq = (const float*)d_in[4];
    const float* Wk = (const float*)d_in[5];
    const float* bk = (const float*)d_in[6];
    const float* Wv = (const float*)d_in[7];
    const float* bv = (const float*)d_in[8];
    const float* Wo = (const float*)d_in[9];
    const float* bo = (const float*)d_in[10];

    float* out  = (float*)d_out;
    float* attn = out + OUT_ELEMS;

    cudaFuncSetAttribute(gemm5<true>,  cudaFuncAttributeMaxDynamicSharedMemorySize, GT_SMEM);
    cudaFuncSetAttribute(gemm5<false>, cudaFuncAttributeMaxDynamicSharedMemorySize, GT_SMEM);
    cudaFuncSetAttribute(attn_fused, cudaFuncAttributeMaxDynamicSharedMemorySize, ATTN_SMEM);

    // 1. cvt q,k,v -> g_X
    repackQKV_k<<<3 * N4 / 256, 256>>>((const float4*)q, (const float4*)k,
                                       (const float4*)v);
    // 2. transpose+cvt all 4 weights
    wT4_k<<<dim3(HD/32, HD/32, 4), dim3(32, 8)>>>(Wq, Wk, Wv, Wo);
    // 3. Q,K,V projections in one launch
    gemm5<true><<<dim3(HD/128, MTOT/128, 3), 256, GT_SMEM>>>(bq, bk, bv, nullptr);
    // 4. V -> V^T cvt
    vT_k<<<dim3(64, NBH), dim3(32, 8)>>>();
    // 5. fused attention: scores + softmax + attn write + P@V -> ctx
    attn_fused<<<dim3(HS/32, NBH), 256, ATTN_SMEM>>>(attn);
    // 6. out = ctx @ Wo + bo
    gemm5<false><<<dim3(HD/128, MTOT/128), 256, GT_SMEM>>>(bo, nullptr, nullptr, out);
}

// round 8
// speedup vs baseline: 1.2233x; 1.0130x over previous
#include <cuda_runtime.h>
#include <cstdint>

// Problem constants
#define HB   4
#define HS   1024
#define HD   1024
#define HH   16
#define HDK  64
#define MTOT (HB*HS)          // 4096
#define NBH  (HB*HH)          // 64
#define OUT_ELEMS (MTOT*HD)   // 4194304

// Scratch (allocation-free device globals) — all tf32-converted fp32 bits
__device__ float g_X[3*MTOT*HD];     // cvt inputs q,k,v (A); slot0 reused for ctx
__device__ float g_W[4*HD*HD];       // W^T [n][k] (B)
__device__ float g_Q[NBH*HS*HDK];    // [bh][s][d] row-major, pre-scaled (A)
__device__ float g_K[NBH*HS*HDK];    // [bh][key][d] (B)
__device__ float g_Vf[NBH*HS*HDK];   // [bh][s][d] plain fp32
__device__ float g_VT[NBH*HDK*HS];   // [bh][d][s] (B)

// ---------------------------------------------------------------------------
// helpers
// ---------------------------------------------------------------------------
__device__ __forceinline__ uint32_t smem_u32(const void* p) {
    uint32_t a;
    asm("{ .reg .u64 t; cvta.to.shared.u64 t, %1; cvt.u32.u64 %0, t; }"
        : "=r"(a) : "l"(p));
    return a;
}
__device__ __forceinline__ uint32_t cvt_tf32(float f) {
    uint32_t o;
    asm("cvt.rna.tf32.f32 %0, %1;" : "=r"(o) : "f"(f));
    return o;
}
__device__ __forceinline__ void ldmx4(uint32_t* r, uint32_t addr) {
    asm volatile("ldmatrix.sync.aligned.m8n8.x4.shared.b16 {%0,%1,%2,%3}, [%4];"
        : "=r"(r[0]), "=r"(r[1]), "=r"(r[2]), "=r"(r[3]) : "r"(addr));
}
__device__ __forceinline__ void mma_tf32(float* c, uint32_t a0, uint32_t a1,
                                         uint32_t a2, uint32_t a3,
                                         uint32_t b0, uint32_t b1) {
    asm volatile(
        "mma.sync.aligned.m16n8k8.row.col.f32.tf32.tf32.f32 "
        "{%0,%1,%2,%3}, {%4,%5,%6,%7}, {%8,%9}, {%0,%1,%2,%3};"
        : "+f"(c[0]), "+f"(c[1]), "+f"(c[2]), "+f"(c[3])
        : "r"(a0), "r"(a1), "r"(a2), "r"(a3), "r"(b0), "r"(b1));
}
#define CP16(dst, src) asm volatile("cp.async.cg.shared.global [%0], [%1], 16;" :: "r"(dst), "l"(src))
#define CP_COMMIT()    asm volatile("cp.async.commit_group;" ::: "memory")
#define CP_WAIT1()     asm volatile("cp.async.wait_group 1;" ::: "memory")
#define CP_WAIT0()     asm volatile("cp.async.wait_group 0;" ::: "memory")

// ---------------------------------------------------------------------------
// q,k,v fp32 -> tf32-cvt fp32 into g_X, one launch
// ---------------------------------------------------------------------------
#define N4 (OUT_ELEMS/4)
__global__ __launch_bounds__(256)
void repackQKV_k(const float4* __restrict__ q, const float4* __restrict__ k,
                 const float4* __restrict__ v)
{
    int i = blockIdx.x * 256 + threadIdx.x;          // 0 .. 3*N4
    int z = i / N4, j = i - z * N4;
    const float4* src = (z == 0) ? q : (z == 1) ? k : v;
    float4 val = src[j];
    uint4 o;
    o.x = cvt_tf32(val.x); o.y = cvt_tf32(val.y);
    o.z = cvt_tf32(val.z); o.w = cvt_tf32(val.w);
    ((uint4*)(g_X + (size_t)z * OUT_ELEMS))[j] = o;
}

// ---------------------------------------------------------------------------
// All 4 weights: W[k][n] fp32 -> W^T [n][k] tf32-cvt
// ---------------------------------------------------------------------------
__global__ __launch_bounds__(256)
void wT4_k(const float* __restrict__ Wq, const float* __restrict__ Wk,
           const float* __restrict__ Wv, const float* __restrict__ Wo)
{
    __shared__ float t[32][33];
    const int z = blockIdx.z;
    const float* W = (z == 0) ? Wq : (z == 1) ? Wk : (z == 2) ? Wv : Wo;
    uint32_t* dst = (uint32_t*)(g_W + (size_t)z * HD * HD);
    int k0 = blockIdx.y * 32, n0 = blockIdx.x * 32;
    int tx = threadIdx.x, ty = threadIdx.y;   // (32, 8)
#pragma unroll
    for (int j = 0; j < 32; j += 8)
        t[ty + j][tx] = W[(size_t)(k0 + ty + j) * HD + n0 + tx];
    __syncthreads();
#pragma unroll
    for (int j = 0; j < 32; j += 8)
        dst[(size_t)(n0 + ty + j) * HD + k0 + tx] = cvt_tf32(t[tx][ty + j]);
}

// ---------------------------------------------------------------------------
// g_Vf [bh][s][d] -> g_VT [bh][d][s] tf32-cvt
// ---------------------------------------------------------------------------
__global__ __launch_bounds__(256)
void vT_k()
{
    __shared__ float t[32][33];
    int bh = blockIdx.y;
    int s0 = (blockIdx.x & 31) * 32;
    int d0 = (blockIdx.x >> 5) * 32;
    int tx = threadIdx.x, ty = threadIdx.y;   // (32, 8)
    const float* V = g_Vf + (size_t)bh * HS * HDK;
#pragma unroll
    for (int j = 0; j < 32; j += 8)
        t[ty + j][tx] = V[(size_t)(s0 + ty + j) * HDK + d0 + tx];
    __syncthreads();
    uint32_t* dst = (uint32_t*)(g_VT + (size_t)bh * HDK * HS);
#pragma unroll
    for (int j = 0; j < 32; j += 8)
        dst[(size_t)(d0 + ty + j) * HS + s0 + tx] = cvt_tf32(t[tx][ty + j]);
}

// ---------------------------------------------------------------------------
// Dense tf32 GEMM (BM=128,BN=128,BK=32), cp.async 3-stage, ldmatrix frags.
// 512 threads, 16 warps = 4x4 warp grid, 32x32 per warp.
// PROJ=true: blockIdx.z in {0,1,2} = Q/K/V with fused epilogues.
// PROJ=false: out = ctx @ Wo + bo, fp32 row-major.
// ---------------------------------------------------------------------------
#define GSTRB 144                    // 32 floats data + 16B pad (stride ≡ 4 mod 32 words)
#define GMATB (128*GSTRB)            // 18432
#define GSTG  (2*GMATB)              // 36864 (A + B)
#define GT_SMEM (3*GSTG)             // 110592

template<bool PROJ>
__global__ __launch_bounds__(512, 1)
void gemm5(const float* __restrict__ b0, const float* __restrict__ b1,
           const float* __restrict__ b2, float* __restrict__ outp)
{
    extern __shared__ char sm[];
    const uint32_t sb = smem_u32(sm);
    const int z = PROJ ? blockIdx.z : 3;
    const int tid = threadIdx.x;
    const int wid = tid >> 5, lane = tid & 31;
    const int wm = wid & 3, wn = wid >> 2;
    const int m0 = blockIdx.y * 128, n0 = blockIdx.x * 128;

    const float* X = g_X + (PROJ ? (size_t)z * OUT_ELEMS : 0);
    const float* W = g_W + (size_t)z * HD * HD;
    const float* bias = PROJ ? ((z == 0) ? b0 : (z == 1) ? b1 : b2) : b0;

    float acc[8][4];
#pragma unroll
    for (int i = 0; i < 8; i++)
#pragma unroll
        for (int j = 0; j < 4; j++) acc[i][j] = 0.f;

    auto cp_stage = [&](int st, int k0) {
        uint32_t d = sb + st * GSTG;
#pragma unroll
        for (int t = 0; t < 2; ++t) {
            int i = tid + t * 512;          // 0..1023
            int r = i >> 3, c = i & 7;
            CP16(d + r*GSTRB + c*16,         X + (size_t)(m0 + r)*HD + k0 + c*4);
            CP16(d + GMATB + r*GSTRB + c*16, W + (size_t)(n0 + r)*HD + k0 + c*4);
        }
        CP_COMMIT();
    };

    const int mrow = (lane & 7) | ((lane & 16) >> 1);   // 0..15
    const int mcol = (lane & 8) ? 16 : 0;               // byte offset

    cp_stage(0, 0);
    cp_stage(1, 32);

    int s = 0;
#pragma unroll 1
    for (int c = 0; c < 32; ++c) {
        if (c < 31) { CP_WAIT1(); } else { CP_WAIT0(); }
        __syncthreads();
        if (c + 2 < 32) cp_stage((s + 2) % 3, (c + 2) * 32);

        const uint32_t stA = sb + s * GSTG;
        const uint32_t stB = stA + GMATB;
#pragma unroll
        for (int ks = 0; ks < 4; ++ks) {
            uint32_t a[2][4], b[2][4];
#pragma unroll
            for (int fm = 0; fm < 2; ++fm)
                ldmx4(a[fm], stA + (wm*32 + fm*16 + mrow)*GSTRB + ks*32 + mcol);
#pragma unroll
            for (int gp = 0; gp < 2; ++gp)
                ldmx4(b[gp], stB + (wn*32 + gp*16 + mrow)*GSTRB + ks*32 + mcol);
#pragma unroll
            for (int fm = 0; fm < 2; ++fm)
#pragma unroll
                for (int g = 0; g < 4; ++g) {
                    const int gp = g >> 1, sel = (g & 1) * 2;
                    mma_tf32(acc[fm*4 + g], a[fm][0], a[fm][2], a[fm][1], a[fm][3],
                             b[gp][sel], b[gp][sel + 1]);
                }
        }
        s = (s + 1) % 3;
    }

    // epilogue
#pragma unroll
    for (int fm = 0; fm < 2; ++fm)
#pragma unroll
        for (int fn = 0; fn < 4; ++fn) {
            const float* cc = acc[fm*4 + fn];
            const int m = m0 + wm*32 + fm*16 + (lane >> 2);
            const int n = n0 + wn*32 + fn*8 + (lane & 3)*2;
            float2 bv = *(const float2*)&bias[n];
            float v0 = cc[0] + bv.x, v1 = cc[1] + bv.y;    // row m
            float v2 = cc[2] + bv.x, v3 = cc[3] + bv.y;    // row m+8
            if (!PROJ) {
                *(float2*)&outp[(size_t)m * HD + n]       = make_float2(v0, v1);
                *(float2*)&outp[(size_t)(m + 8) * HD + n] = make_float2(v2, v3);
            } else {
                const int b = m >> 10, sq = m & 1023;
                const int h = n >> 6,  d  = n & 63;
                size_t rbase = (((size_t)(b*HH + h))*HS + sq) * HDK;
                if (z == 2) {
                    *(float2*)&g_Vf[rbase + d]            = make_float2(v0, v1);
                    *(float2*)&g_Vf[rbase + 8*HDK + d]    = make_float2(v2, v3);
                } else {
                    float sc = (z == 0) ? 0.125f : 1.0f;
                    float* Y = (z == 0) ? g_Q : g_K;
                    uint2 u0 = make_uint2(cvt_tf32(v0 * sc), cvt_tf32(v1 * sc));
                    uint2 u1 = make_uint2(cvt_tf32(v2 * sc), cvt_tf32(v3 * sc));
                    *(uint2*)&Y[rbase + d]         = u0;
                    *(uint2*)&Y[rbase + 8*HDK + d] = u1;
                }
            }
        }
}

// ---------------------------------------------------------------------------
// Fused attention (tf32, ldmatrix, 512 threads = 16 warps):
// QK^T -> softmax (attn streamed) -> P@V (k-split across warp halves).
// CTA = (32 q rows, bh).
// ---------------------------------------------------------------------------
#define SSTR 1032
#define SSB (32*SSTR*4)                 // 132096
#define OFF_Q SSB
#define QSTRB 272                       // 64 floats + 16B pad (68 words ≡ 4 mod 32)
#define OFF_K (OFF_Q + 32*QSTRB)        // 140800
#define KMATB (128*QSTRB)               // 34816 per stage
#define OFF_P SSB                       // overlay phase 3
#define PSTRB 528                       // 128 floats + 16B pad (132 ≡ 4 mod 32)
#define OFF_VT (OFF_P + 32*PSTRB)       // 148992
#define VTMATB (64*PSTRB)               // 33792 per stage
#define ATTN_SMEM (OFF_VT + 2*VTMATB)   // 216576

__global__ __launch_bounds__(512, 1)
void attn_fused(float* __restrict__ attn_out)
{
    extern __shared__ char sm[];
    const uint32_t sb = smem_u32(sm);
    float* Ss = (float*)sm;

    const int tid = threadIdx.x;
    const int wid = tid >> 5, lane = tid & 31;
    const int bh = blockIdx.y;
    const int q0 = blockIdx.x * 32;
    const int mrow = (lane & 7) | ((lane & 16) >> 1);
    const int mcol = (lane & 8) ? 16 : 0;

    const float* Qg  = g_Q  + (size_t)bh * HS * HDK;
    const float* Kg  = g_K  + (size_t)bh * HS * HDK;
    const float* VTg = g_VT + (size_t)bh * HDK * HS;

    // Q tile 32x64 (1 chunk/thread)
    {
        int r = tid >> 4, c = tid & 15;
        *(uint4*)(sm + OFF_Q + r*QSTRB + c*16) =
            *(const uint4*)(Qg + (size_t)(q0 + r)*HDK + c*4);
    }

    auto cp_K = [&](int st, int kt) {
        uint32_t d = sb + OFF_K + st * KMATB;
#pragma unroll
        for (int t = 0; t < 4; ++t) {
            int i = tid + t * 512;
            int r = i >> 4, c = i & 15;
            CP16(d + r*QSTRB + c*16, Kg + (size_t)(kt*128 + r)*HDK + c*4);
        }
        CP_COMMIT();
    };
    auto cp_VT = [&](int st, int kt) {
        uint32_t d = sb + OFF_VT + st * VTMATB;
#pragma unroll
        for (int t = 0; t < 4; ++t) {
            int i = tid + t * 512;
            int r = i >> 5, c = i & 31;
            CP16(d + r*PSTRB + c*16, VTg + (size_t)r*HS + kt*128 + c*4);
        }
        CP_COMMIT();
    };

    cp_K(0, 0);

    // ---- Phase 1: scores ----
    const int wm = wid & 1;        // 16 q rows
    const int wn = wid >> 1;       // 8 groups x 16 keys
#pragma unroll 1
    for (int kt = 0; kt < 8; ++kt) {
        const int s = kt & 1;
        if (kt < 7) cp_K(s ^ 1, kt + 1);
        if (kt < 7) { CP_WAIT1(); } else { CP_WAIT0(); }
        __syncthreads();

        float acc[2][4];
#pragma unroll
        for (int i = 0; i < 2; i++)
#pragma unroll
            for (int j = 0; j < 4; j++) acc[i][j] = 0.f;

        const uint32_t stK = sb + OFF_K + s * KMATB;
#pragma unroll
        for (int ks = 0; ks < 8; ++ks) {
            uint32_t a[4], b[4];
            ldmx4(a, sb + OFF_Q + (wm*16 + mrow)*QSTRB + ks*32 + mcol);
            ldmx4(b, stK + (wn*16 + mrow)*QSTRB + ks*32 + mcol);
#pragma unroll
            for (int g = 0; g < 2; ++g)
                mma_tf32(acc[g], a[0], a[2], a[1], a[3], b[g*2], b[g*2+1]);
        }
#pragma unroll
        for (int fn = 0; fn < 2; ++fn) {
            int row = wm*16 + (lane >> 2);
            int col = kt*128 + wn*16 + fn*8 + (lane & 3)*2;
            *(float2*)&Ss[(size_t)row * SSTR + col]       = make_float2(acc[fn][0], acc[fn][1]);
            *(float2*)&Ss[(size_t)(row + 8) * SSTR + col] = make_float2(acc[fn][2], acc[fn][3]);
        }
        __syncthreads();
    }

    // prefetch first VT tile (K fully consumed; overlaps softmax)
    cp_VT(0, 0);

    // ---- Phase 2: softmax (16 threads/row); stream attn out ----
    {
        const int row = tid >> 4;
        const int t16 = tid & 15;
        float* srow = Ss + (size_t)row * SSTR;

        float mx = -1e30f;
#pragma unroll
        for (int i = 0; i < 16; i++) {
            float4 v = *(const float4*)&srow[t16*4 + i*64];
            mx = fmaxf(mx, fmaxf(fmaxf(v.x, v.y), fmaxf(v.z, v.w)));
        }
#pragma unroll
        for (int o = 8; o >= 1; o >>= 1)
            mx = fmaxf(mx, __shfl_xor_sync(0xffffffffu, mx, o));

        float sum = 0.f;
#pragma unroll
        for (int i = 0; i < 16; i++) {
            float4 v = *(float4*)&srow[t16*4 + i*64];
            v.x = __expf(v.x - mx); v.y = __expf(v.y - mx);
            v.z = __expf(v.z - mx); v.w = __expf(v.w - mx);
            sum += v.x + v.y + v.z + v.w;
            *(float4*)&srow[t16*4 + i*64] = v;
        }
#pragma unroll
        for (int o = 8; o >= 1; o >>= 1)
            sum += __shfl_xor_sync(0xffffffffu, sum, o);
        float inv = 1.f / sum;

        float* arow = attn_out + ((size_t)bh * HS + q0 + row) * HS;
#pragma unroll
        for (int i = 0; i < 16; i++) {
            float4 v = *(float4*)&srow[t16*4 + i*64];
            v.x *= inv; v.y *= inv; v.z *= inv; v.w *= inv;
            *(float4*)&srow[t16*4 + i*64] = v;
            __stcs((float4*)&arow[t16*4 + i*64], v);       // streaming store
        }
    }
    __syncthreads();

    // ---- Phase 3: ctx = P @ V (k-split: warps 0-7 ks 0-7, warps 8-15 ks 8-15)
    const int kh  = wid >> 3;              // k half
    const int wmp = wid & 1;               // 16 q rows
    const int wnp = (wid >> 1) & 3;        // 4 groups x 16 d
    float acc2[2][4];
#pragma unroll
    for (int i = 0; i < 2; i++)
#pragma unroll
        for (int j = 0; j < 4; j++) acc2[i][j] = 0.f;

#pragma unroll 1
    for (int kt = 0; kt < 8; ++kt) {
        const int s = kt & 1;
        // P chunk 32x128 -> tf32 cvt into sP (4 float2 per thread)
#pragma unroll
        for (int i = 0; i < 4; ++i) {
            int p = tid + i*512;
            int row = p >> 6, cp = p & 63;
            float2 v = *(const float2*)&Ss[(size_t)row * SSTR + kt*128 + cp*2];
            uint2 u = make_uint2(cvt_tf32(v.x), cvt_tf32(v.y));
            *(uint2*)(sm + OFF_P + row*PSTRB + cp*8) = u;
        }
        if (kt < 7) cp_VT(s ^ 1, kt + 1);
        if (kt < 7) { CP_WAIT1(); } else { CP_WAIT0(); }
        __syncthreads();

        const uint32_t stVT = sb + OFF_VT + s * VTMATB;
#pragma unroll
        for (int ks2 = 0; ks2 < 8; ++ks2) {
            const int ks = kh*8 + ks2;
            uint32_t a[4], b[4];
            ldmx4(a, sb + OFF_P + (wmp*16 + mrow)*PSTRB + ks*32 + mcol);
            ldmx4(b, stVT + (wnp*16 + mrow)*PSTRB + ks*32 + mcol);
#pragma unroll
            for (int g = 0; g < 2; ++g)
                mma_tf32(acc2[g], a[0], a[2], a[1], a[3], b[g*2], b[g*2+1]);
        }
        __syncthreads();
    }

    // cross-half reduction: warps 8-15 dump partials, warps 0-7 add
    {
        float* red = (float*)sm;           // Ss region is dead now
        if (wid >= 8) {
            float* d = red + ((size_t)(wid - 8) * 32 + lane) * 8;
            *(float4*)d       = make_float4(acc2[0][0], acc2[0][1], acc2[0][2], acc2[0][3]);
            *(float4*)(d + 4) = make_float4(acc2[1][0], acc2[1][1], acc2[1][2], acc2[1][3]);
        }
        __syncthreads();
        if (wid < 8) {
            const float* d = red + ((size_t)wid * 32 + lane) * 8;
            float4 p0 = *(const float4*)d;
            float4 p1 = *(const float4*)(d + 4);
            acc2[0][0] += p0.x; acc2[0][1] += p0.y; acc2[0][2] += p0.z; acc2[0][3] += p0.w;
            acc2[1][0] += p1.x; acc2[1][1] += p1.y; acc2[1][2] += p1.z; acc2[1][3] += p1.w;
        }
    }

    // epilogue (warps 0-7): ctx tf32-cvt -> g_X slot0 row-major [4096][1024]
    if (wid < 8) {
        const int b = bh >> 4, h = bh & 15;
#pragma unroll
        for (int fn = 0; fn < 2; ++fn) {
            int s  = q0 + wmp*16 + (lane >> 2);
            int cl = h*64 + wnp*16 + fn*8 + (lane & 3)*2;
            size_t o0 = (size_t)(b*HS + s)     * HD + cl;
            size_t o1 = (size_t)(b*HS + s + 8) * HD + cl;
            uint2 u0 = make_uint2(cvt_tf32(acc2[fn][0]), cvt_tf32(acc2[fn][1]));
            uint2 u1 = make_uint2(cvt_tf32(acc2[fn][2]), cvt_tf32(acc2[fn][3]));
            *(uint2*)&g_X[o0] = u0;
            *(uint2*)&g_X[o1] = u1;
        }
    }
}

// ---------------------------------------------------------------------------
extern "C" void kernel_launch(void* const* d_in, const int* in_sizes, int n_in,
                              void* d_out, int out_size)
{
    const float* q  = (const float*)d_in[0];
    const float* k  = (const float*)d_in[1];
    const float* v  = (const float*)d_in[2];
    const float* Wq = (const float*)d_in[3];
    const float* bq = (const float*)d_in[4];
    const float* Wk = (const float*)d_in[5];
    const float* bk = (const float*)d_in[6];
    const float* Wv = (const float*)d_in[7];
    const float* bv = (const float*)d_in[8];
    const float* Wo = (const float*)d_in[9];
    const float* bo = (const float*)d_in[10];

    float* out  = (float*)d_out;
    float* attn = out + OUT_ELEMS;

    cudaFuncSetAttribute(gemm5<true>,  cudaFuncAttributeMaxDynamicSharedMemorySize, GT_SMEM);
    cudaFuncSetAttribute(gemm5<false>, cudaFuncAttributeMaxDynamicSharedMemorySize, GT_SMEM);
    cudaFuncSetAttribute(attn_fused, cudaFuncAttributeMaxDynamicSharedMemorySize, ATTN_SMEM);

    // 1. cvt q,k,v -> g_X
    repackQKV_k<<<3 * N4 / 256, 256>>>((const float4*)q, (const float4*)k,
                                       (const float4*)v);
    // 2. transpose+cvt all 4 weights
    wT4_k<<<dim3(HD/32, HD/32, 4), dim3(32, 8)>>>(Wq, Wk, Wv, Wo);
    // 3. Q,K,V projections in one launch
    gemm5<true><<<dim3(HD/128, MTOT/128, 3), 512, GT_SMEM>>>(bq, bk, bv, nullptr);
    // 4. V -> V^T cvt
    vT_k<<<dim3(64, NBH), dim3(32, 8)>>>();
    // 5. fused attention: scores + softmax + attn write + P@V -> ctx
    attn_fused<<<dim3(HS/32, NBH), 512, ATTN_SMEM>>>(attn);
    // 6. out = ctx @ Wo + bo
    gemm5<false><<<dim3(HD/128, MTOT/128), 512, GT_SMEM>>>(bo, nullptr, nullptr, out);
}

// round 9
// speedup vs baseline: 1.3938x; 1.1394x over previous
#include <cuda_runtime.h>
#include <cstdint>

// Problem constants
#define HB   4
#define HS   1024
#define HD   1024
#define HH   16
#define HDK  64
#define MTOT (HB*HS)          // 4096
#define NBH  (HB*HH)          // 64
#define OUT_ELEMS (MTOT*HD)   // 4194304

// Scratch (allocation-free device globals) — all tf32-converted fp32 bits
__device__ float g_X[3*MTOT*HD];     // cvt inputs q,k,v (A); slot0 reused for ctx
__device__ float g_W[4*HD*HD];       // W^T [n][k] (B)
__device__ float g_Q[NBH*HS*HDK];    // [bh][s][d] row-major, pre-scaled (A)
__device__ float g_K[NBH*HS*HDK];    // [bh][key][d] (B)
__device__ float g_Vf[NBH*HS*HDK];   // [bh][s][d] plain fp32
__device__ float g_VT[NBH*HDK*HS];   // [bh][d][s] (B)

// ---------------------------------------------------------------------------
// helpers
// ---------------------------------------------------------------------------
__device__ __forceinline__ uint32_t smem_u32(const void* p) {
    uint32_t a;
    asm("{ .reg .u64 t; cvta.to.shared.u64 t, %1; cvt.u32.u64 %0, t; }"
        : "=r"(a) : "l"(p));
    return a;
}
__device__ __forceinline__ uint32_t cvt_tf32(float f) {
    uint32_t o;
    asm("cvt.rna.tf32.f32 %0, %1;" : "=r"(o) : "f"(f));
    return o;
}
__device__ __forceinline__ void ldmx4(uint32_t* r, uint32_t addr) {
    asm volatile("ldmatrix.sync.aligned.m8n8.x4.shared.b16 {%0,%1,%2,%3}, [%4];"
        : "=r"(r[0]), "=r"(r[1]), "=r"(r[2]), "=r"(r[3]) : "r"(addr));
}
__device__ __forceinline__ void mma_tf32(float* c, uint32_t a0, uint32_t a1,
                                         uint32_t a2, uint32_t a3,
                                         uint32_t b0, uint32_t b1) {
    asm volatile(
        "mma.sync.aligned.m16n8k8.row.col.f32.tf32.tf32.f32 "
        "{%0,%1,%2,%3}, {%4,%5,%6,%7}, {%8,%9}, {%0,%1,%2,%3};"
        : "+f"(c[0]), "+f"(c[1]), "+f"(c[2]), "+f"(c[3])
        : "r"(a0), "r"(a1), "r"(a2), "r"(a3), "r"(b0), "r"(b1));
}
#define CP16(dst, src) asm volatile("cp.async.cg.shared.global [%0], [%1], 16;" :: "r"(dst), "l"(src))
#define CP_COMMIT()    asm volatile("cp.async.commit_group;" ::: "memory")
#define CP_WAIT1()     asm volatile("cp.async.wait_group 1;" ::: "memory")
#define CP_WAIT0()     asm volatile("cp.async.wait_group 0;" ::: "memory")

// ---------------------------------------------------------------------------
// q,k,v fp32 -> tf32-cvt fp32 into g_X, one launch
// ---------------------------------------------------------------------------
#define N4 (OUT_ELEMS/4)
__global__ __launch_bounds__(256)
void repackQKV_k(const float4* __restrict__ q, const float4* __restrict__ k,
                 const float4* __restrict__ v)
{
    int i = blockIdx.x * 256 + threadIdx.x;          // 0 .. 3*N4
    int z = i / N4, j = i - z * N4;
    const float4* src = (z == 0) ? q : (z == 1) ? k : v;
    float4 val = src[j];
    uint4 o;
    o.x = cvt_tf32(val.x); o.y = cvt_tf32(val.y);
    o.z = cvt_tf32(val.z); o.w = cvt_tf32(val.w);
    ((uint4*)(g_X + (size_t)z * OUT_ELEMS))[j] = o;
}

// ---------------------------------------------------------------------------
// All 4 weights: W[k][n] fp32 -> W^T [n][k] tf32-cvt
// ---------------------------------------------------------------------------
__global__ __launch_bounds__(256)
void wT4_k(const float* __restrict__ Wq, const float* __restrict__ Wk,
           const float* __restrict__ Wv, const float* __restrict__ Wo)
{
    __shared__ float t[32][33];
    const int z = blockIdx.z;
    const float* W = (z == 0) ? Wq : (z == 1) ? Wk : (z == 2) ? Wv : Wo;
    uint32_t* dst = (uint32_t*)(g_W + (size_t)z * HD * HD);
    int k0 = blockIdx.y * 32, n0 = blockIdx.x * 32;
    int tx = threadIdx.x, ty = threadIdx.y;   // (32, 8)
#pragma unroll
    for (int j = 0; j < 32; j += 8)
        t[ty + j][tx] = W[(size_t)(k0 + ty + j) * HD + n0 + tx];
    __syncthreads();
#pragma unroll
    for (int j = 0; j < 32; j += 8)
        dst[(size_t)(n0 + ty + j) * HD + k0 + tx] = cvt_tf32(t[tx][ty + j]);
}

// ---------------------------------------------------------------------------
// g_Vf [bh][s][d] -> g_VT [bh][d][s] tf32-cvt
// ---------------------------------------------------------------------------
__global__ __launch_bounds__(256)
void vT_k()
{
    __shared__ float t[32][33];
    int bh = blockIdx.y;
    int s0 = (blockIdx.x & 31) * 32;
    int d0 = (blockIdx.x >> 5) * 32;
    int tx = threadIdx.x, ty = threadIdx.y;   // (32, 8)
    const float* V = g_Vf + (size_t)bh * HS * HDK;
#pragma unroll
    for (int j = 0; j < 32; j += 8)
        t[ty + j][tx] = V[(size_t)(s0 + ty + j) * HDK + d0 + tx];
    __syncthreads();
    uint32_t* dst = (uint32_t*)(g_VT + (size_t)bh * HDK * HS);
#pragma unroll
    for (int j = 0; j < 32; j += 8)
        dst[(size_t)(d0 + ty + j) * HS + s0 + tx] = cvt_tf32(t[tx][ty + j]);
}

// ---------------------------------------------------------------------------
// Dense tf32 GEMM (BM=256,BN=128,BK=32), cp.async 3-stage, ldmatrix frags.
// 512 threads, 16 warps = 4(m)x4(n) grid, warp tile 64x32 (6 LDSM : 16 MMA).
// PROJ=true: blockIdx.z in {0,1,2} = Q/K/V with fused epilogues.
// PROJ=false: out = ctx @ Wo + bo, fp32 row-major.
// ---------------------------------------------------------------------------
#define GSTRB 144                    // 32 floats + 16B pad (stride ≡ 4 mod 32 words)
#define GA_BYTES (256*GSTRB)         // 36864
#define GB_BYTES (128*GSTRB)         // 18432
#define GSTG (GA_BYTES + GB_BYTES)   // 55296
#define GT_SMEM (3*GSTG)             // 165888

template<bool PROJ>
__global__ __launch_bounds__(512, 1)
void gemm5(const float* __restrict__ b0, const float* __restrict__ b1,
           const float* __restrict__ b2, float* __restrict__ outp)
{
    extern __shared__ char sm[];
    const uint32_t sb = smem_u32(sm);
    const int z = PROJ ? blockIdx.z : 3;
    const int tid = threadIdx.x;
    const int wid = tid >> 5, lane = tid & 31;
    const int wm = wid & 3, wn = wid >> 2;          // 4x4 warp grid
    const int m0 = blockIdx.y * 256, n0 = blockIdx.x * 128;

    const float* X = g_X + (PROJ ? (size_t)z * OUT_ELEMS : 0);
    const float* W = g_W + (size_t)z * HD * HD;
    const float* bias = PROJ ? ((z == 0) ? b0 : (z == 1) ? b1 : b2) : b0;

    float acc[16][4];
#pragma unroll
    for (int i = 0; i < 16; i++)
#pragma unroll
        for (int j = 0; j < 4; j++) acc[i][j] = 0.f;

    auto cp_stage = [&](int st, int k0) {
        uint32_t d = sb + st * GSTG;
#pragma unroll
        for (int t = 0; t < 4; ++t) {               // A: 2048 granules
            int i = tid + t * 512;
            int r = i >> 3, c = i & 7;
            CP16(d + r*GSTRB + c*16, X + (size_t)(m0 + r)*HD + k0 + c*4);
        }
#pragma unroll
        for (int t = 0; t < 2; ++t) {               // B: 1024 granules
            int i = tid + t * 512;
            int r = i >> 3, c = i & 7;
            CP16(d + GA_BYTES + r*GSTRB + c*16, W + (size_t)(n0 + r)*HD + k0 + c*4);
        }
        CP_COMMIT();
    };

    const int mrow = (lane & 7) | ((lane & 16) >> 1);   // 0..15
    const int mcol = (lane & 8) ? 16 : 0;               // byte offset

    cp_stage(0, 0);
    cp_stage(1, 32);

    int s = 0;
#pragma unroll 1
    for (int c = 0; c < 32; ++c) {
        if (c < 31) { CP_WAIT1(); } else { CP_WAIT0(); }
        __syncthreads();
        if (c + 2 < 32) cp_stage((s + 2) % 3, (c + 2) * 32);

        const uint32_t stA = sb + s * GSTG;
        const uint32_t stB = stA + GA_BYTES;
#pragma unroll
        for (int ks = 0; ks < 4; ++ks) {
            uint32_t a[4][4], b[2][4];
#pragma unroll
            for (int fm = 0; fm < 4; ++fm)
                ldmx4(a[fm], stA + (wm*64 + fm*16 + mrow)*GSTRB + ks*32 + mcol);
#pragma unroll
            for (int gp = 0; gp < 2; ++gp)
                ldmx4(b[gp], stB + (wn*32 + gp*16 + mrow)*GSTRB + ks*32 + mcol);
#pragma unroll
            for (int fm = 0; fm < 4; ++fm)
#pragma unroll
                for (int g = 0; g < 4; ++g) {
                    const int gp = g >> 1, sel = (g & 1) * 2;
                    mma_tf32(acc[fm*4 + g], a[fm][0], a[fm][2], a[fm][1], a[fm][3],
                             b[gp][sel], b[gp][sel + 1]);
                }
        }
        s = (s + 1) % 3;
    }

    // epilogue
#pragma unroll
    for (int fm = 0; fm < 4; ++fm)
#pragma unroll
        for (int fn = 0; fn < 4; ++fn) {
            const float* cc = acc[fm*4 + fn];
            const int m = m0 + wm*64 + fm*16 + (lane >> 2);
            const int n = n0 + wn*32 + fn*8 + (lane & 3)*2;
            float2 bv = *(const float2*)&bias[n];
            float v0 = cc[0] + bv.x, v1 = cc[1] + bv.y;    // row m
            float v2 = cc[2] + bv.x, v3 = cc[3] + bv.y;    // row m+8
            if (!PROJ) {
                *(float2*)&outp[(size_t)m * HD + n]       = make_float2(v0, v1);
                *(float2*)&outp[(size_t)(m + 8) * HD + n] = make_float2(v2, v3);
            } else {
                const int b = m >> 10, sq = m & 1023;
                const int h = n >> 6,  d  = n & 63;
                size_t rbase = (((size_t)(b*HH + h))*HS + sq) * HDK;
                if (z == 2) {
                    *(float2*)&g_Vf[rbase + d]            = make_float2(v0, v1);
                    *(float2*)&g_Vf[rbase + 8*HDK + d]    = make_float2(v2, v3);
                } else {
                    float sc = (z == 0) ? 0.125f : 1.0f;
                    float* Y = (z == 0) ? g_Q : g_K;
                    uint2 u0 = make_uint2(cvt_tf32(v0 * sc), cvt_tf32(v1 * sc));
                    uint2 u1 = make_uint2(cvt_tf32(v2 * sc), cvt_tf32(v3 * sc));
                    *(uint2*)&Y[rbase + d]         = u0;
                    *(uint2*)&Y[rbase + 8*HDK + d] = u1;
                }
            }
        }
}

// ---------------------------------------------------------------------------
// Fused attention (tf32, ldmatrix, 512 threads = 16 warps):
// Phase1 QK^T with hoisted Q frags -> softmax (attn streamed) ->
// Phase3 P@V (4-way k-split, warp tile 16q x 32d) -> ctx.
// CTA = (32 q rows, bh).
// ---------------------------------------------------------------------------
#define SSTR 1032
#define SSB (32*SSTR*4)                 // 132096
#define OFF_Q SSB
#define QSTRB 272                       // 64 floats + 16B pad (68 ≡ 4 mod 32)
#define OFF_K (OFF_Q + 32*QSTRB)        // 140800
#define KMATB (128*QSTRB)               // 34816 per stage
#define OFF_P SSB                       // overlay phase 3
#define PSTRB 528                       // 128 floats + 16B pad (132 ≡ 4 mod 32)
#define OFF_VT (OFF_P + 32*PSTRB)       // 148992
#define VTMATB (64*PSTRB)               // 33792 per stage
#define ATTN_SMEM (OFF_VT + 2*VTMATB)   // 216576

__global__ __launch_bounds__(512, 1)
void attn_fused(float* __restrict__ attn_out)
{
    extern __shared__ char sm[];
    const uint32_t sb = smem_u32(sm);
    float* Ss = (float*)sm;

    const int tid = threadIdx.x;
    const int wid = tid >> 5, lane = tid & 31;
    const int bh = blockIdx.y;
    const int q0 = blockIdx.x * 32;
    const int mrow = (lane & 7) | ((lane & 16) >> 1);
    const int mcol = (lane & 8) ? 16 : 0;

    const float* Qg  = g_Q  + (size_t)bh * HS * HDK;
    const float* Kg  = g_K  + (size_t)bh * HS * HDK;
    const float* VTg = g_VT + (size_t)bh * HDK * HS;

    // Q tile 32x64 (1 chunk/thread)
    {
        int r = tid >> 4, c = tid & 15;
        *(uint4*)(sm + OFF_Q + r*QSTRB + c*16) =
            *(const uint4*)(Qg + (size_t)(q0 + r)*HDK + c*4);
    }

    auto cp_K = [&](int st, int kt) {
        uint32_t d = sb + OFF_K + st * KMATB;
#pragma unroll
        for (int t = 0; t < 4; ++t) {
            int i = tid + t * 512;
            int r = i >> 4, c = i & 15;
            CP16(d + r*QSTRB + c*16, Kg + (size_t)(kt*128 + r)*HDK + c*4);
        }
        CP_COMMIT();
    };
    auto cp_VT = [&](int st, int kt) {
        uint32_t d = sb + OFF_VT + st * VTMATB;
#pragma unroll
        for (int t = 0; t < 4; ++t) {
            int i = tid + t * 512;
            int r = i >> 5, c = i & 31;
            CP16(d + r*PSTRB + c*16, VTg + (size_t)r*HS + kt*128 + c*4);
        }
        CP_COMMIT();
    };

    cp_K(0, 0);
    __syncthreads();                    // Q tile visible

    // ---- hoist Q fragments for whole phase 1 (8 ks x 4 regs) ----
    const int wm = wid & 1;             // 16 q rows
    const int wn = wid >> 1;            // 8 groups x 16 keys
    uint32_t qf[8][4];
#pragma unroll
    for (int ks = 0; ks < 8; ++ks)
        ldmx4(qf[ks], sb + OFF_Q + (wm*16 + mrow)*QSTRB + ks*32 + mcol);

    // ---- Phase 1: scores ----
#pragma unroll 1
    for (int kt = 0; kt < 8; ++kt) {
        const int s = kt & 1;
        if (kt < 7) cp_K(s ^ 1, kt + 1);
        if (kt < 7) { CP_WAIT1(); } else { CP_WAIT0(); }
        __syncthreads();

        float acc[2][4];
#pragma unroll
        for (int i = 0; i < 2; i++)
#pragma unroll
            for (int j = 0; j < 4; j++) acc[i][j] = 0.f;

        const uint32_t stK = sb + OFF_K + s * KMATB;
#pragma unroll
        for (int ks = 0; ks < 8; ++ks) {
            uint32_t b[4];
            ldmx4(b, stK + (wn*16 + mrow)*QSTRB + ks*32 + mcol);
#pragma unroll
            for (int g = 0; g < 2; ++g)
                mma_tf32(acc[g], qf[ks][0], qf[ks][2], qf[ks][1], qf[ks][3],
                         b[g*2], b[g*2+1]);
        }
#pragma unroll
        for (int fn = 0; fn < 2; ++fn) {
            int row = wm*16 + (lane >> 2);
            int col = kt*128 + wn*16 + fn*8 + (lane & 3)*2;
            *(float2*)&Ss[(size_t)row * SSTR + col]       = make_float2(acc[fn][0], acc[fn][1]);
            *(float2*)&Ss[(size_t)(row + 8) * SSTR + col] = make_float2(acc[fn][2], acc[fn][3]);
        }
        __syncthreads();
    }

    // prefetch first VT tile (K fully consumed; overlaps softmax)
    cp_VT(0, 0);

    // ---- Phase 2: softmax (16 threads/row); stream attn out ----
    {
        const int row = tid >> 4;
        const int t16 = tid & 15;
        float* srow = Ss + (size_t)row * SSTR;

        float mx = -1e30f;
#pragma unroll
        for (int i = 0; i < 16; i++) {
            float4 v = *(const float4*)&srow[t16*4 + i*64];
            mx = fmaxf(mx, fmaxf(fmaxf(v.x, v.y), fmaxf(v.z, v.w)));
        }
#pragma unroll
        for (int o = 8; o >= 1; o >>= 1)
            mx = fmaxf(mx, __shfl_xor_sync(0xffffffffu, mx, o));

        float sum = 0.f;
#pragma unroll
        for (int i = 0; i < 16; i++) {
            float4 v = *(float4*)&srow[t16*4 + i*64];
            v.x = __expf(v.x - mx); v.y = __expf(v.y - mx);
            v.z = __expf(v.z - mx); v.w = __expf(v.w - mx);
            sum += v.x + v.y + v.z + v.w;
            *(float4*)&srow[t16*4 + i*64] = v;
        }
#pragma unroll
        for (int o = 8; o >= 1; o >>= 1)
            sum += __shfl_xor_sync(0xffffffffu, sum, o);
        float inv = 1.f / sum;

        float* arow = attn_out + ((size_t)bh * HS + q0 + row) * HS;
#pragma unroll
        for (int i = 0; i < 16; i++) {
            float4 v = *(float4*)&srow[t16*4 + i*64];
            v.x *= inv; v.y *= inv; v.z *= inv; v.w *= inv;
            *(float4*)&srow[t16*4 + i*64] = v;
            __stcs((float4*)&arow[t16*4 + i*64], v);       // streaming store
        }
    }
    __syncthreads();

    // ---- Phase 3: ctx = P @ V (4-way k-split; warp tile 16q x 32d) ----
    const int kq  = wid >> 2;              // ks quarter 0..3
    const int wmp = wid & 1;               // 16 q rows
    const int wnp = (wid >> 1) & 1;        // 2 groups x 32 d
    float acc2[4][4];
#pragma unroll
    for (int i = 0; i < 4; i++)
#pragma unroll
        for (int j = 0; j < 4; j++) acc2[i][j] = 0.f;

#pragma unroll 1
    for (int kt = 0; kt < 8; ++kt) {
        const int s = kt & 1;
        // P chunk 32x128 -> tf32 cvt into sP (4 float2 per thread)
#pragma unroll
        for (int i = 0; i < 4; ++i) {
            int p = tid + i*512;
            int row = p >> 6, cp = p & 63;
            float2 v = *(const float2*)&Ss[(size_t)row * SSTR + kt*128 + cp*2];
            uint2 u = make_uint2(cvt_tf32(v.x), cvt_tf32(v.y));
            *(uint2*)(sm + OFF_P + row*PSTRB + cp*8) = u;
        }
        if (kt < 7) cp_VT(s ^ 1, kt + 1);
        if (kt < 7) { CP_WAIT1(); } else { CP_WAIT0(); }
        __syncthreads();

        const uint32_t stVT = sb + OFF_VT + s * VTMATB;
#pragma unroll
        for (int ks2 = 0; ks2 < 4; ++ks2) {
            const int ks = kq*4 + ks2;
            uint32_t a[4], b[2][4];
            ldmx4(a, sb + OFF_P + (wmp*16 + mrow)*PSTRB + ks*32 + mcol);
#pragma unroll
            for (int gp = 0; gp < 2; ++gp)
                ldmx4(b[gp], stVT + (wnp*32 + gp*16 + mrow)*PSTRB + ks*32 + mcol);
#pragma unroll
            for (int g = 0; g < 4; ++g) {
                const int gp = g >> 1, sel = (g & 1) * 2;
                mma_tf32(acc2[g], a[0], a[2], a[1], a[3], b[gp][sel], b[gp][sel+1]);
            }
        }
        __syncthreads();
    }

    // cross-quarter reduction: kq 1..3 dump partials, kq 0 adds
    {
        float* red = (float*)sm;           // Ss region is dead now
        const int grp = wmp*2 + wnp;       // 0..3
        if (kq > 0) {
            float* d = red + (((size_t)(kq - 1) * 4 + grp) * 32 + lane) * 16;
#pragma unroll
            for (int f = 0; f < 4; ++f)
                *(float4*)(d + f*4) = make_float4(acc2[f][0], acc2[f][1],
                                                  acc2[f][2], acc2[f][3]);
        }
        __syncthreads();
        if (kq == 0) {
#pragma unroll
            for (int q = 0; q < 3; ++q) {
                const float* d = red + (((size_t)q * 4 + grp) * 32 + lane) * 16;
#pragma unroll
                for (int f = 0; f < 4; ++f) {
                    float4 p = *(const float4*)(d + f*4);
                    acc2[f][0] += p.x; acc2[f][1] += p.y;
                    acc2[f][2] += p.z; acc2[f][3] += p.w;
                }
            }
        }
    }

    // epilogue (kq==0 warps): ctx tf32-cvt -> g_X slot0 row-major [4096][1024]
    if (kq == 0) {
        const int b = bh >> 4, h = bh & 15;
#pragma unroll
        for (int fn = 0; fn < 4; ++fn) {
            int s  = q0 + wmp*16 + (lane >> 2);
            int cl = h*64 + wnp*32 + fn*8 + (lane & 3)*2;
            size_t o0 = (size_t)(b*HS + s)     * HD + cl;
            size_t o1 = (size_t)(b*HS + s + 8) * HD + cl;
            uint2 u0 = make_uint2(cvt_tf32(acc2[fn][0]), cvt_tf32(acc2[fn][1]));
            uint2 u1 = make_uint2(cvt_tf32(acc2[fn][2]), cvt_tf32(acc2[fn][3]));
            *(uint2*)&g_X[o0] = u0;
            *(uint2*)&g_X[o1] = u1;
        }
    }
}

// ---------------------------------------------------------------------------
extern "C" void kernel_launch(void* const* d_in, const int* in_sizes, int n_in,
                              void* d_out, int out_size)
{
    const float* q  = (const float*)d_in[0];
    const float* k  = (const float*)d_in[1];
    const float* v  = (const float*)d_in[2];
    const float* Wq = (const float*)d_in[3];
    const float* bq = (const float*)d_in[4];
    const float* Wk = (const float*)d_in[5];
    const float* bk = (const float*)d_in[6];
    const float* Wv = (const float*)d_in[7];
    const float* bv = (const float*)d_in[8];
    const float* Wo = (const float*)d_in[9];
    const float* bo = (const float*)d_in[10];

    float* out  = (float*)d_out;
    float* attn = out + OUT_ELEMS;

    cudaFuncSetAttribute(gemm5<true>,  cudaFuncAttributeMaxDynamicSharedMemorySize, GT_SMEM);
    cudaFuncSetAttribute(gemm5<false>, cudaFuncAttributeMaxDynamicSharedMemorySize, GT_SMEM);
    cudaFuncSetAttribute(attn_fused, cudaFuncAttributeMaxDynamicSharedMemorySize, ATTN_SMEM);

    // 1. cvt q,k,v -> g_X
    repackQKV_k<<<3 * N4 / 256, 256>>>((const float4*)q, (const float4*)k,
                                       (const float4*)v);
    // 2. transpose+cvt all 4 weights
    wT4_k<<<dim3(HD/32, HD/32, 4), dim3(32, 8)>>>(Wq, Wk, Wv, Wo);
    // 3. Q,K,V projections in one launch
    gemm5<true><<<dim3(HD/128, MTOT/256, 3), 512, GT_SMEM>>>(bq, bk, bv, nullptr);
    // 4. V -> V^T cvt
    vT_k<<<dim3(64, NBH), dim3(32, 8)>>>();
    // 5. fused attention: scores + softmax + attn write + P@V -> ctx
    attn_fused<<<dim3(HS/32, NBH), 512, ATTN_SMEM>>>(attn);
    // 6. out = ctx @ Wo + bo
    gemm5<false><<<dim3(HD/128, MTOT/256), 512, GT_SMEM>>>(bo, nullptr, nullptr, out);
}